// round 2
// baseline (speedup 1.0000x reference)
#include <cuda_runtime.h>
#include <math.h>

// Problem constants
#define BB 2
#define MM 2048
#define DD 1024
#define HH 16
#define DH 64
#define FF 2624
#define NTOK (BB*MM)           // 4096
#define QKV_N (3*DD)           // 3072
#define WI_N (2*FF)            // 5248

// ---------------- scratch (device globals; no allocation allowed) -------------
__device__ float g_xn  [NTOK*DD];        // LN1 out, reused nowhere after QKV
__device__ float g_q   [NTOK*DD];        // [B,H,M,DH]
__device__ float g_k   [NTOK*DD];
__device__ float g_v   [NTOK*DD];
__device__ float g_attn[NTOK*DD];        // [B,M,D]
__device__ float g_xres[NTOK*DD];        // x after attention residual
__device__ float g_h   [NTOK*DD];        // LN2 out
__device__ float g_g   [NTOK*WI_N];      // wi output
__device__ float g_act [NTOK*FF];        // geglu output

// ---------------- LayerNorm -------------------------------------------------
__inline__ __device__ float warpsum(float v) {
    #pragma unroll
    for (int o = 16; o; o >>= 1) v += __shfl_xor_sync(0xffffffff, v, o);
    return v;
}

__global__ __launch_bounds__(256) void ln_kernel(
    const float* __restrict__ x, const float* __restrict__ w,
    const float* __restrict__ b, float* __restrict__ out)
{
    __shared__ float red[2][8];
    int row = blockIdx.x;
    const float4* xr = (const float4*)(x + (size_t)row * DD);
    float4 v = xr[threadIdx.x];
    float s  = v.x + v.y + v.z + v.w;
    float ss = v.x*v.x + v.y*v.y + v.z*v.z + v.w*v.w;
    s = warpsum(s); ss = warpsum(ss);
    int wid = threadIdx.x >> 5, lid = threadIdx.x & 31;
    if (lid == 0) { red[0][wid] = s; red[1][wid] = ss; }
    __syncthreads();
    if (wid == 0) {
        float a = (lid < 8) ? red[0][lid] : 0.f;
        float c = (lid < 8) ? red[1][lid] : 0.f;
        a = warpsum(a); c = warpsum(c);
        if (lid == 0) { red[0][0] = a; red[1][0] = c; }
    }
    __syncthreads();
    float mean = red[0][0] * (1.0f/DD);
    float var  = red[1][0] * (1.0f/DD) - mean*mean;
    float rstd = rsqrtf(var + 1e-5f);
    float4 wv = ((const float4*)w)[threadIdx.x];
    float4 bv = ((const float4*)b)[threadIdx.x];
    float4 o;
    o.x = (v.x - mean)*rstd*wv.x + bv.x;
    o.y = (v.y - mean)*rstd*wv.y + bv.y;
    o.z = (v.z - mean)*rstd*wv.z + bv.z;
    o.w = (v.w - mean)*rstd*wv.w + bv.w;
    ((float4*)(out + (size_t)row * DD))[threadIdx.x] = o;
}

// ---------------- SGEMM: C[n,j] = sum_k A[n,k]*W[j,k]  (both row-major) ------
// 128x128 block, K-tile 8, 256 threads, 8x8 micro-tile per thread.
// MODE 0: C = acc (plain write, ldc=Ndim)
// MODE 1: QKV scatter: acc+bias -> q/k/v in [B,H,M,DH]
// MODE 2: C = acc + resid (residual add)
template<int MODE>
__global__ __launch_bounds__(256) void sgemm_kernel(
    const float* __restrict__ A, const float* __restrict__ W,
    const float* __restrict__ bias, const float* __restrict__ resid,
    float* __restrict__ C,
    float* __restrict__ qout, float* __restrict__ kout, float* __restrict__ vout,
    int Ndim, int Kdim)
{
    __shared__ float As[8][128];
    __shared__ float Bs[8][128];
    int tid = threadIdx.x;
    int m0 = blockIdx.y * 128;
    int n0 = blockIdx.x * 128;
    int ty = tid >> 4, tx = tid & 15;

    float acc[8][8];
    #pragma unroll
    for (int i = 0; i < 8; i++)
        #pragma unroll
        for (int j = 0; j < 8; j++) acc[i][j] = 0.f;

    int arow = tid >> 1;
    int acol = (tid & 1) * 4;
    const float* Aptr = A + (size_t)(m0 + arow) * Kdim + acol;
    const float* Wptr = W + (size_t)(n0 + arow) * Kdim + acol;

    for (int k0 = 0; k0 < Kdim; k0 += 8) {
        float4 av = *(const float4*)(Aptr + k0);
        float4 wv = *(const float4*)(Wptr + k0);
        As[acol+0][arow] = av.x; As[acol+1][arow] = av.y;
        As[acol+2][arow] = av.z; As[acol+3][arow] = av.w;
        Bs[acol+0][arow] = wv.x; Bs[acol+1][arow] = wv.y;
        Bs[acol+2][arow] = wv.z; Bs[acol+3][arow] = wv.w;
        __syncthreads();
        #pragma unroll
        for (int kk = 0; kk < 8; kk++) {
            float a[8], b[8];
            *(float4*)(a)     = *(const float4*)&As[kk][ty*8];
            *(float4*)(a + 4) = *(const float4*)&As[kk][ty*8 + 4];
            *(float4*)(b)     = *(const float4*)&Bs[kk][tx*8];
            *(float4*)(b + 4) = *(const float4*)&Bs[kk][tx*8 + 4];
            #pragma unroll
            for (int i = 0; i < 8; i++)
                #pragma unroll
                for (int j = 0; j < 8; j++)
                    acc[i][j] += a[i] * b[j];
        }
        __syncthreads();
    }

    if (MODE == 1) {
        #pragma unroll
        for (int i = 0; i < 8; i++) {
            int n = m0 + ty*8 + i;
            int b = n >> 11, m = n & 2047;
            #pragma unroll
            for (int j = 0; j < 8; j++) {
                int col = n0 + tx*8 + j;
                float val = acc[i][j] + bias[col];
                int which = col >> 10, rem = col & 1023;
                int hh = rem >> 6, d = rem & 63;
                float* dst = (which == 0) ? qout : (which == 1) ? kout : vout;
                dst[(size_t)(((b << 4) + hh) * MM + m) * DH + d] = val;
            }
        }
    } else {
        #pragma unroll
        for (int i = 0; i < 8; i++) {
            size_t row = (size_t)(m0 + ty*8 + i);
            #pragma unroll
            for (int j = 0; j < 8; j++) {
                int col = n0 + tx*8 + j;
                float val = acc[i][j];
                if (MODE == 2) val += resid[row * Ndim + col];
                C[row * Ndim + col] = val;
            }
        }
    }
}

// ---------------- RoPE (in-place on q,k in [B,H,M,DH]) -----------------------
__global__ void rope_kernel(float* __restrict__ q, float* __restrict__ k)
{
    int gid = blockIdx.x * blockDim.x + threadIdx.x;   // over B*H*M*32
    int i = gid & 31;
    int r = gid >> 5;          // row over B*H*M
    int m = r & (MM - 1);
    // inv_freq = 10000^{-(2i)/64}; compute in double then round (tracks jax f32)
    float invf = (float)exp2(-(double)i * (13.287712379549449 / 32.0));
    float angle = (float)m * invf;
    float sv, cv;
    sincosf(angle, &sv, &cv);
    size_t base = (size_t)r * DH + i;
    float q1 = q[base], q2 = q[base + 32];
    q[base]      = q1 * cv - q2 * sv;
    q[base + 32] = q1 * sv + q2 * cv;
    float k1 = k[base], k2 = k[base + 32];
    k[base]      = k1 * cv - k2 * sv;
    k[base + 32] = k1 * sv + k2 * cv;
}

// ---------------- Flash attention: 1 query per thread, 32-key tiles ----------
#define TQ 128
#define TK 32
__global__ __launch_bounds__(128) void attn_kernel(
    const float* __restrict__ Q, const float* __restrict__ Kg,
    const float* __restrict__ Vg, const int* __restrict__ amask,
    float* __restrict__ out)
{
    __shared__ float Ks[TK][DH];
    __shared__ float Vs[TK][DH];
    __shared__ int   msk[TK];

    int bh = blockIdx.y;               // b*H + h
    int b = bh >> 4;
    int h = bh & 15;
    int m = blockIdx.x * TQ + threadIdx.x;

    const float* qrow = Q + ((size_t)bh * MM + m) * DH;
    float q[DH];
    #pragma unroll
    for (int i = 0; i < 16; i++) ((float4*)q)[i] = ((const float4*)qrow)[i];

    float o[DH];
    #pragma unroll
    for (int d = 0; d < DH; d++) o[d] = 0.f;
    float mx = -1e30f, l = 0.f;

    const float* Kbase = Kg + (size_t)bh * MM * DH;
    const float* Vbase = Vg + (size_t)bh * MM * DH;

    for (int kt = 0; kt < MM; kt += TK) {
        // cooperative load of K/V tile (TK*DH floats each = 512 float4)
        for (int t = threadIdx.x; t < TK * (DH/4); t += TQ) {
            ((float4*)&Ks[0][0])[t] = ((const float4*)(Kbase + (size_t)kt * DH))[t];
            ((float4*)&Vs[0][0])[t] = ((const float4*)(Vbase + (size_t)kt * DH))[t];
        }
        if (threadIdx.x < TK) msk[threadIdx.x] = amask[b * MM + kt + threadIdx.x];
        __syncthreads();

        float s[TK];
        float tmax = mx;
        #pragma unroll 4
        for (int j = 0; j < TK; j++) {
            float accd = 0.f;
            const float4* kr = (const float4*)Ks[j];
            #pragma unroll
            for (int d4 = 0; d4 < 16; d4++) {
                float4 kv = kr[d4];
                accd += q[4*d4+0]*kv.x + q[4*d4+1]*kv.y + q[4*d4+2]*kv.z + q[4*d4+3]*kv.w;
            }
            s[j] = msk[j] ? accd * 0.125f : -1e30f;
            tmax = fmaxf(tmax, s[j]);
        }
        float corr = __expf(mx - tmax);
        mx = tmax;
        float psum = 0.f;
        #pragma unroll
        for (int j = 0; j < TK; j++) { s[j] = __expf(s[j] - mx); psum += s[j]; }
        l = l * corr + psum;
        #pragma unroll
        for (int d = 0; d < DH; d++) o[d] *= corr;
        #pragma unroll 4
        for (int j = 0; j < TK; j++) {
            float p = s[j];
            const float4* vr = (const float4*)Vs[j];
            #pragma unroll
            for (int d4 = 0; d4 < 16; d4++) {
                float4 vv = vr[d4];
                o[4*d4+0] += p*vv.x; o[4*d4+1] += p*vv.y;
                o[4*d4+2] += p*vv.z; o[4*d4+3] += p*vv.w;
            }
        }
        __syncthreads();
    }

    float inv = 1.0f / l;
    float* orow = out + ((size_t)(b * MM + m)) * DD + h * DH;
    #pragma unroll
    for (int d4 = 0; d4 < 16; d4++) {
        float4 ov;
        ov.x = o[4*d4+0]*inv; ov.y = o[4*d4+1]*inv;
        ov.z = o[4*d4+2]*inv; ov.w = o[4*d4+3]*inv;
        ((float4*)orow)[d4] = ov;
    }
}

// ---------------- GeGLU: act[n,f] = gelu(g[n,f]) * g[n,FF+f] -----------------
__global__ void geglu_kernel(const float* __restrict__ g, float* __restrict__ act)
{
    int n = blockIdx.x;
    const float* gr = g + (size_t)n * WI_N;
    float* ar = act + (size_t)n * FF;
    for (int f = threadIdx.x; f < FF; f += blockDim.x) {
        float x = gr[f];
        float gate = gr[f + FF];
        float ge = 0.5f * x * (1.0f + erff(x * 0.7071067811865476f));
        ar[f] = ge * gate;
    }
}

// ---------------- launch ------------------------------------------------------
extern "C" void kernel_launch(void* const* d_in, const int* in_sizes, int n_in,
                              void* d_out, int out_size)
{
    const float* hs     = (const float*)d_in[0];
    const int*   amask  = (const int*)  d_in[1];
    const float* ln1w   = (const float*)d_in[2];
    const float* ln1b   = (const float*)d_in[3];
    const float* wqkv_w = (const float*)d_in[4];
    const float* wqkv_b = (const float*)d_in[5];
    const float* wo_w   = (const float*)d_in[6];
    const float* ln2w   = (const float*)d_in[7];
    const float* ln2b   = (const float*)d_in[8];
    const float* wi_w   = (const float*)d_in[9];
    const float* womlp  = (const float*)d_in[10];
    float* out = (float*)d_out;

    float *xn, *q, *k, *v, *attn, *xres, *h, *gg, *act;
    cudaGetSymbolAddress((void**)&xn,   g_xn);
    cudaGetSymbolAddress((void**)&q,    g_q);
    cudaGetSymbolAddress((void**)&k,    g_k);
    cudaGetSymbolAddress((void**)&v,    g_v);
    cudaGetSymbolAddress((void**)&attn, g_attn);
    cudaGetSymbolAddress((void**)&xres, g_xres);
    cudaGetSymbolAddress((void**)&h,    g_h);
    cudaGetSymbolAddress((void**)&gg,   g_g);
    cudaGetSymbolAddress((void**)&act,  g_act);

    // 1. LN1
    ln_kernel<<<NTOK, 256>>>(hs, ln1w, ln1b, xn);

    // 2. QKV gemm, scatter to q/k/v [B,H,M,DH]
    sgemm_kernel<1><<<dim3(QKV_N/128, NTOK/128), 256>>>(
        xn, wqkv_w, wqkv_b, nullptr, nullptr, q, k, v, QKV_N, DD);

    // 3. RoPE in-place on q,k
    rope_kernel<<<(BB*HH*MM*32)/256, 256>>>(q, k);

    // 4. Flash attention -> attn [B,M,D]
    attn_kernel<<<dim3(MM/TQ, BB*HH), TQ>>>(q, k, v, amask, attn);

    // 5. O projection + residual -> xres
    sgemm_kernel<2><<<dim3(DD/128, NTOK/128), 256>>>(
        attn, wo_w, nullptr, hs, xres, nullptr, nullptr, nullptr, DD, DD);

    // 6. LN2
    ln_kernel<<<NTOK, 256>>>(xres, ln2w, ln2b, h);

    // 7. Wi gemm -> g [NTOK, 2*FF]
    sgemm_kernel<0><<<dim3(WI_N/128, NTOK/128), 256>>>(
        h, wi_w, nullptr, nullptr, gg, nullptr, nullptr, nullptr, WI_N, DD);

    // 8. GeGLU
    geglu_kernel<<<NTOK, 256>>>(gg, act);

    // 9. Wo_mlp gemm + residual -> out
    sgemm_kernel<2><<<dim3(DD/128, NTOK/128), 256>>>(
        act, womlp, nullptr, xres, out, nullptr, nullptr, nullptr, DD, FF);
}

// round 3
// speedup vs baseline: 1.0565x; 1.0565x over previous
#include <cuda_runtime.h>
#include <math.h>
#include <stdint.h>

// Problem constants
#define BB 2
#define MM 2048
#define DD 1024
#define HH 16
#define DH 64
#define FF 2624
#define NTOK (BB*MM)           // 4096
#define QKV_N (3*DD)           // 3072
#define WI_N (2*FF)            // 5248

// ---------------- packed f32x2 helpers (Blackwell FFMA2 path) ----------------
struct alignas(16) U2 { unsigned long long a, b; };

__device__ __forceinline__ void ffma2(unsigned long long& c,
                                      unsigned long long x,
                                      unsigned long long y) {
    asm("fma.rn.f32x2 %0, %1, %2, %0;" : "+l"(c) : "l"(x), "l"(y));
}
__device__ __forceinline__ void fmul2(unsigned long long& c, unsigned long long x) {
    asm("mul.rn.f32x2 %0, %0, %1;" : "+l"(c) : "l"(x));
}
__device__ __forceinline__ unsigned long long pack2(float x, float y) {
    unsigned long long r;
    asm("mov.b64 %0, {%1,%2};" : "=l"(r) : "f"(x), "f"(y));
    return r;
}
__device__ __forceinline__ float2 unpack2(unsigned long long v) {
    float2 r;
    asm("mov.b64 {%0,%1}, %2;" : "=f"(r.x), "=f"(r.y) : "l"(v));
    return r;
}

// ---------------- scratch (device globals; no allocation allowed) -------------
__device__ float g_xn  [NTOK*DD];
__device__ float g_q   [NTOK*DD];        // [B,H,M,DH]
__device__ float g_k   [NTOK*DD];
__device__ float g_v   [NTOK*DD];
__device__ float g_attn[NTOK*DD];        // [B,M,D]
__device__ float g_xres[NTOK*DD];
__device__ float g_h   [NTOK*DD];
__device__ float g_g   [NTOK*WI_N];
__device__ float g_act [NTOK*FF];

// ---------------- LayerNorm -------------------------------------------------
__inline__ __device__ float warpsum(float v) {
    #pragma unroll
    for (int o = 16; o; o >>= 1) v += __shfl_xor_sync(0xffffffff, v, o);
    return v;
}

__global__ __launch_bounds__(256) void ln_kernel(
    const float* __restrict__ x, const float* __restrict__ w,
    const float* __restrict__ b, float* __restrict__ out)
{
    __shared__ float red[2][8];
    int row = blockIdx.x;
    const float4* xr = (const float4*)(x + (size_t)row * DD);
    float4 v = xr[threadIdx.x];
    float s  = v.x + v.y + v.z + v.w;
    float ss = v.x*v.x + v.y*v.y + v.z*v.z + v.w*v.w;
    s = warpsum(s); ss = warpsum(ss);
    int wid = threadIdx.x >> 5, lid = threadIdx.x & 31;
    if (lid == 0) { red[0][wid] = s; red[1][wid] = ss; }
    __syncthreads();
    if (wid == 0) {
        float a = (lid < 8) ? red[0][lid] : 0.f;
        float c = (lid < 8) ? red[1][lid] : 0.f;
        a = warpsum(a); c = warpsum(c);
        if (lid == 0) { red[0][0] = a; red[1][0] = c; }
    }
    __syncthreads();
    float mean = red[0][0] * (1.0f/DD);
    float var  = red[1][0] * (1.0f/DD) - mean*mean;
    float rstd = rsqrtf(var + 1e-5f);
    float4 wv = ((const float4*)w)[threadIdx.x];
    float4 bv = ((const float4*)b)[threadIdx.x];
    float4 o;
    o.x = (v.x - mean)*rstd*wv.x + bv.x;
    o.y = (v.y - mean)*rstd*wv.y + bv.y;
    o.z = (v.z - mean)*rstd*wv.z + bv.z;
    o.w = (v.w - mean)*rstd*wv.w + bv.w;
    ((float4*)(out + (size_t)row * DD))[threadIdx.x] = o;
}

// ---------------- SGEMM (FFMA2): C[n,j] = sum_k A[n,k]*W[j,k] ---------------
// 128x128 block, K-tile 8, 256 threads, 8x8 micro-tile per thread.
// MODE 0: C = acc; MODE 1: QKV scatter + bias; MODE 2: C = acc + resid
template<int MODE>
__global__ __launch_bounds__(256) void sgemm_kernel(
    const float* __restrict__ A, const float* __restrict__ W,
    const float* __restrict__ bias, const float* __restrict__ resid,
    float* __restrict__ C,
    float* __restrict__ qout, float* __restrict__ kout, float* __restrict__ vout,
    int Ndim, int Kdim)
{
    __shared__ float As[8][128];
    __shared__ float Bs[8][128];
    int tid = threadIdx.x;
    int m0 = blockIdx.y * 128;
    int n0 = blockIdx.x * 128;
    int ty = tid >> 4, tx = tid & 15;

    unsigned long long acc2[8][4];
    #pragma unroll
    for (int i = 0; i < 8; i++)
        #pragma unroll
        for (int j = 0; j < 4; j++) acc2[i][j] = 0ULL;

    int arow = tid >> 1;
    int acol = (tid & 1) * 4;
    const float* Aptr = A + (size_t)(m0 + arow) * Kdim + acol;
    const float* Wptr = W + (size_t)(n0 + arow) * Kdim + acol;

    float4 av = *(const float4*)Aptr;
    float4 wv = *(const float4*)Wptr;

    for (int k0 = 0; k0 < Kdim; k0 += 8) {
        As[acol+0][arow] = av.x; As[acol+1][arow] = av.y;
        As[acol+2][arow] = av.z; As[acol+3][arow] = av.w;
        Bs[acol+0][arow] = wv.x; Bs[acol+1][arow] = wv.y;
        Bs[acol+2][arow] = wv.z; Bs[acol+3][arow] = wv.w;
        __syncthreads();

        // prefetch next K-tile while computing this one
        if (k0 + 8 < Kdim) {
            av = *(const float4*)(Aptr + k0 + 8);
            wv = *(const float4*)(Wptr + k0 + 8);
        }

        #pragma unroll
        for (int kk = 0; kk < 8; kk++) {
            float a[8];
            *(float4*)(a)     = *(const float4*)&As[kk][ty*8];
            *(float4*)(a + 4) = *(const float4*)&As[kk][ty*8 + 4];
            U2 b01 = *(const U2*)&Bs[kk][tx*8];
            U2 b23 = *(const U2*)&Bs[kk][tx*8 + 4];
            #pragma unroll
            for (int i = 0; i < 8; i++) {
                unsigned long long ad = pack2(a[i], a[i]);
                ffma2(acc2[i][0], ad, b01.a);
                ffma2(acc2[i][1], ad, b01.b);
                ffma2(acc2[i][2], ad, b23.a);
                ffma2(acc2[i][3], ad, b23.b);
            }
        }
        __syncthreads();
    }

    if (MODE == 1) {
        #pragma unroll
        for (int i = 0; i < 8; i++) {
            int n = m0 + ty*8 + i;
            int b = n >> 11, m = n & 2047;
            #pragma unroll
            for (int j2 = 0; j2 < 4; j2++) {
                float2 p = unpack2(acc2[i][j2]);
                #pragma unroll
                for (int half = 0; half < 2; half++) {
                    int col = n0 + tx*8 + 2*j2 + half;
                    float val = (half ? p.y : p.x) + bias[col];
                    int which = col >> 10, rem = col & 1023;
                    int hh = rem >> 6, d = rem & 63;
                    float* dst = (which == 0) ? qout : (which == 1) ? kout : vout;
                    dst[(size_t)(((b << 4) + hh) * MM + m) * DH + d] = val;
                }
            }
        }
    } else {
        #pragma unroll
        for (int i = 0; i < 8; i++) {
            size_t row = (size_t)(m0 + ty*8 + i);
            #pragma unroll
            for (int j2 = 0; j2 < 4; j2++) {
                float2 p = unpack2(acc2[i][j2]);
                int col = n0 + tx*8 + 2*j2;
                float v0 = p.x, v1 = p.y;
                if (MODE == 2) {
                    v0 += resid[row * Ndim + col];
                    v1 += resid[row * Ndim + col + 1];
                }
                C[row * Ndim + col]     = v0;
                C[row * Ndim + col + 1] = v1;
            }
        }
    }
}

// ---------------- RoPE (in-place on q,k in [B,H,M,DH]) -----------------------
__global__ void rope_kernel(float* __restrict__ q, float* __restrict__ k)
{
    int gid = blockIdx.x * blockDim.x + threadIdx.x;   // over B*H*M*32
    int i = gid & 31;
    int r = gid >> 5;          // row over B*H*M
    int m = r & (MM - 1);
    float invf = (float)exp2(-(double)i * (13.287712379549449 / 32.0));
    float angle = (float)m * invf;
    float sv, cv;
    sincosf(angle, &sv, &cv);
    size_t base = (size_t)r * DH + i;
    float q1 = q[base], q2 = q[base + 32];
    q[base]      = q1 * cv - q2 * sv;
    q[base + 32] = q1 * sv + q2 * cv;
    float k1 = k[base], k2 = k[base + 32];
    k[base]      = k1 * cv - k2 * sv;
    k[base + 32] = k1 * sv + k2 * cv;
}

// ---------------- Flash attention (FFMA2): 1 query/thread, 32-key tiles ------
#define TQ 128
#define TK 32
__global__ __launch_bounds__(128) void attn_kernel(
    const float* __restrict__ Q, const float* __restrict__ Kg,
    const float* __restrict__ Vg, const int* __restrict__ amask,
    float* __restrict__ out)
{
    __shared__ float Ks[TK][DH];
    __shared__ float Vs[TK][DH];
    __shared__ int   msk[TK];

    int bh = blockIdx.y;               // b*H + h
    int b = bh >> 4;
    int h = bh & 15;
    int m = blockIdx.x * TQ + threadIdx.x;

    const float* qrow = Q + ((size_t)bh * MM + m) * DH;
    unsigned long long q2[32];          // 32 packed pairs = 64 floats
    #pragma unroll
    for (int i = 0; i < 16; i++) {
        U2 t = ((const U2*)qrow)[i];
        q2[2*i]   = t.a;
        q2[2*i+1] = t.b;
    }

    unsigned long long o2[32];
    #pragma unroll
    for (int d = 0; d < 32; d++) o2[d] = 0ULL;
    float mx = -1e30f, l = 0.f;

    const float* Kbase = Kg + (size_t)bh * MM * DH;
    const float* Vbase = Vg + (size_t)bh * MM * DH;

    for (int kt = 0; kt < MM; kt += TK) {
        for (int t = threadIdx.x; t < TK * (DH/4); t += TQ) {
            ((float4*)&Ks[0][0])[t] = ((const float4*)(Kbase + (size_t)kt * DH))[t];
            ((float4*)&Vs[0][0])[t] = ((const float4*)(Vbase + (size_t)kt * DH))[t];
        }
        if (threadIdx.x < TK) msk[threadIdx.x] = amask[b * MM + kt + threadIdx.x];
        __syncthreads();

        float s[TK];
        float tmax = mx;
        #pragma unroll 4
        for (int j = 0; j < TK; j++) {
            unsigned long long acc = 0ULL;
            const U2* kr = (const U2*)Ks[j];
            #pragma unroll
            for (int d4 = 0; d4 < 16; d4++) {
                U2 kv = kr[d4];
                ffma2(acc, q2[2*d4],   kv.a);
                ffma2(acc, q2[2*d4+1], kv.b);
            }
            float2 pr = unpack2(acc);
            float accd = pr.x + pr.y;
            s[j] = msk[j] ? accd * 0.125f : -1e30f;
            tmax = fmaxf(tmax, s[j]);
        }
        float corr = __expf(mx - tmax);
        mx = tmax;
        float psum = 0.f;
        #pragma unroll
        for (int j = 0; j < TK; j++) { s[j] = __expf(s[j] - mx); psum += s[j]; }
        l = l * corr + psum;
        unsigned long long corr2 = pack2(corr, corr);
        #pragma unroll
        for (int d = 0; d < 32; d++) fmul2(o2[d], corr2);
        #pragma unroll 4
        for (int j = 0; j < TK; j++) {
            unsigned long long pd = pack2(s[j], s[j]);
            const U2* vr = (const U2*)Vs[j];
            #pragma unroll
            for (int d4 = 0; d4 < 16; d4++) {
                U2 vv = vr[d4];
                ffma2(o2[2*d4],   pd, vv.a);
                ffma2(o2[2*d4+1], pd, vv.b);
            }
        }
        __syncthreads();
    }

    float inv = 1.0f / l;
    unsigned long long inv2 = pack2(inv, inv);
    #pragma unroll
    for (int d = 0; d < 32; d++) fmul2(o2[d], inv2);
    float* orow = out + ((size_t)(b * MM + m)) * DD + h * DH;
    #pragma unroll
    for (int d4 = 0; d4 < 16; d4++) {
        U2 ov;
        ov.a = o2[2*d4];
        ov.b = o2[2*d4+1];
        ((U2*)orow)[d4] = ov;
    }
}

// ---------------- GeGLU -------------------------------------------------------
__global__ void geglu_kernel(const float* __restrict__ g, float* __restrict__ act)
{
    int n = blockIdx.x;
    const float* gr = g + (size_t)n * WI_N;
    float* ar = act + (size_t)n * FF;
    for (int f = threadIdx.x; f < FF; f += blockDim.x) {
        float x = gr[f];
        float gate = gr[f + FF];
        float ge = 0.5f * x * (1.0f + erff(x * 0.7071067811865476f));
        ar[f] = ge * gate;
    }
}

// ---------------- launch ------------------------------------------------------
extern "C" void kernel_launch(void* const* d_in, const int* in_sizes, int n_in,
                              void* d_out, int out_size)
{
    const float* hs     = (const float*)d_in[0];
    const int*   amask  = (const int*)  d_in[1];
    const float* ln1w   = (const float*)d_in[2];
    const float* ln1b   = (const float*)d_in[3];
    const float* wqkv_w = (const float*)d_in[4];
    const float* wqkv_b = (const float*)d_in[5];
    const float* wo_w   = (const float*)d_in[6];
    const float* ln2w   = (const float*)d_in[7];
    const float* ln2b   = (const float*)d_in[8];
    const float* wi_w   = (const float*)d_in[9];
    const float* womlp  = (const float*)d_in[10];
    float* out = (float*)d_out;

    float *xn, *q, *k, *v, *attn, *xres, *h, *gg, *act;
    cudaGetSymbolAddress((void**)&xn,   g_xn);
    cudaGetSymbolAddress((void**)&q,    g_q);
    cudaGetSymbolAddress((void**)&k,    g_k);
    cudaGetSymbolAddress((void**)&v,    g_v);
    cudaGetSymbolAddress((void**)&attn, g_attn);
    cudaGetSymbolAddress((void**)&xres, g_xres);
    cudaGetSymbolAddress((void**)&h,    g_h);
    cudaGetSymbolAddress((void**)&gg,   g_g);
    cudaGetSymbolAddress((void**)&act,  g_act);

    ln_kernel<<<NTOK, 256>>>(hs, ln1w, ln1b, xn);

    sgemm_kernel<1><<<dim3(QKV_N/128, NTOK/128), 256>>>(
        xn, wqkv_w, wqkv_b, nullptr, nullptr, q, k, v, QKV_N, DD);

    rope_kernel<<<(BB*HH*MM*32)/256, 256>>>(q, k);

    attn_kernel<<<dim3(MM/TQ, BB*HH), TQ>>>(q, k, v, amask, attn);

    sgemm_kernel<2><<<dim3(DD/128, NTOK/128), 256>>>(
        attn, wo_w, nullptr, hs, xres, nullptr, nullptr, nullptr, DD, DD);

    ln_kernel<<<NTOK, 256>>>(xres, ln2w, ln2b, h);

    sgemm_kernel<0><<<dim3(WI_N/128, NTOK/128), 256>>>(
        h, wi_w, nullptr, nullptr, gg, nullptr, nullptr, nullptr, WI_N, DD);

    geglu_kernel<<<NTOK, 256>>>(gg, act);

    sgemm_kernel<2><<<dim3(DD/128, NTOK/128), 256>>>(
        act, womlp, nullptr, xres, out, nullptr, nullptr, nullptr, DD, FF);
}

// round 5
// speedup vs baseline: 1.6334x; 1.5460x over previous
#include <cuda_runtime.h>
#include <cuda_bf16.h>
#include <math.h>
#include <stdint.h>

// Problem constants
#define BB 2
#define MM 2048
#define DD 1024
#define HH 16
#define DH 64
#define FF 2624
#define NTOK (BB*MM)           // 4096
#define QKV_N (3*DD)           // 3072
#define WI_N (2*FF)            // 5248

// ---------------- scratch (device globals; no allocation allowed) -------------
__device__ float g_xn  [NTOK*DD];
__device__ float g_q   [NTOK*DD];        // [B,H,M,DH]
__device__ float g_k   [NTOK*DD];
__device__ float g_v   [NTOK*DD];
__device__ float g_attn[NTOK*DD];        // [B,M,D]
__device__ float g_xres[NTOK*DD];
__device__ float g_h   [NTOK*DD];
__device__ float g_g   [NTOK*WI_N];
__device__ float g_act [NTOK*FF];
// bf16x3 split buffers
__device__ __align__(128) __nv_bfloat16 g_a3[(size_t)NTOK * 3 * FF];
__device__ __align__(128) __nv_bfloat16 g_w3[(size_t)WI_N * 3 * DD];

// ---------------- PTX helpers (all base compute_80+, no 'a' features) ---------
__device__ __forceinline__ uint32_t smem_u32(const void* p) {
    uint32_t a;
    asm("{ .reg .u64 t; cvta.to.shared.u64 t, %1; cvt.u32.u64 %0, t; }"
        : "=r"(a) : "l"(p));
    return a;
}
__device__ __forceinline__ void cp16(uint32_t saddr, const void* g) {
    asm volatile("cp.async.cg.shared.global [%0], [%1], 16;" :: "r"(saddr), "l"(g));
}
__device__ __forceinline__ void ldm_x4(uint32_t* r, uint32_t addr) {
    asm volatile("ldmatrix.sync.aligned.m8n8.x4.shared.b16 {%0,%1,%2,%3}, [%4];"
        : "=r"(r[0]), "=r"(r[1]), "=r"(r[2]), "=r"(r[3]) : "r"(addr));
}
__device__ __forceinline__ void mma16816(float* c, const uint32_t* a, const uint32_t* b) {
    asm volatile("mma.sync.aligned.m16n8k16.row.col.f32.bf16.bf16.f32 "
        "{%0,%1,%2,%3}, {%4,%5,%6,%7}, {%8,%9}, {%0,%1,%2,%3};"
        : "+f"(c[0]), "+f"(c[1]), "+f"(c[2]), "+f"(c[3])
        : "r"(a[0]), "r"(a[1]), "r"(a[2]), "r"(a[3]), "r"(b[0]), "r"(b[1]));
}

// ---------------- fp32 -> bf16x3 split ----------------------------------------
// ISW=0 (activation): [hi | lo | hi] ; ISW=1 (weight): [hi | hi | lo]
template<int ISW>
__global__ void split_kernel(const float* __restrict__ X,
                             __nv_bfloat16* __restrict__ Y,
                             int K, int total)
{
    int i = blockIdx.x * 256 + threadIdx.x;
    if (i >= total) return;
    int r = i / K;
    int c = i - r * K;
    float x = X[i];
    __nv_bfloat16 hb = __float2bfloat16(x);
    float h = __bfloat162float(hb);
    __nv_bfloat16 lb = __float2bfloat16(x - h);
    size_t base = (size_t)r * (3 * K) + c;
    Y[base] = hb;
    if (ISW) { Y[base + K] = hb; Y[base + 2*K] = lb; }
    else     { Y[base + K] = lb; Y[base + 2*K] = hb; }
}

// ---------------- bf16 tensor-core GEMM: C[m,n] = sum_k A3[m,k]*W3[n,k] ------
// 128x128 CTA tile, 8 warps (4m x 2n), warp tile 32x64, K-tile 32,
// cp.async double-buffered smem, ldmatrix + mma.sync m16n8k16.
// MODE 0: C = acc; MODE 1: QKV scatter + bias; MODE 2: C = acc + resid
#define PADK 40                      // bf16 elems per smem row (32 + 8 pad)
#define TILE_ELEMS (128*PADK)

template<int MODE>
__global__ __launch_bounds__(256) void bgemm_kernel(
    const __nv_bfloat16* __restrict__ A3, const __nv_bfloat16* __restrict__ W3,
    const float* __restrict__ bias, const float* __restrict__ resid,
    float* __restrict__ C,
    float* __restrict__ qout, float* __restrict__ kout, float* __restrict__ vout,
    int Ndim, int K3)
{
    __shared__ __nv_bfloat16 Asm[2][TILE_ELEMS];
    __shared__ __nv_bfloat16 Bsm[2][TILE_ELEMS];

    const int tid = threadIdx.x;
    const int wid = tid >> 5, lid = tid & 31;
    const int wm = wid >> 1, wn = wid & 1;
    const int m0 = blockIdx.y * 128, n0 = blockIdx.x * 128;

    uint32_t aBase = smem_u32(Asm);
    uint32_t bBase = smem_u32(Bsm);

    const __nv_bfloat16* Ag = A3 + (size_t)m0 * K3;
    const __nv_bfloat16* Wg = W3 + (size_t)n0 * K3;
    const int ntiles = K3 >> 5;

    // cp.async mapping: idx over 512 16B-chunks; row = idx/4, chunk = idx%4
    const int ldr0 = tid >> 2, ldc0 = (tid & 3) * 8;
    const int ldr1 = (tid + 256) >> 2, ldc1 = ldc0;

    float acc[2][8][4];
    #pragma unroll
    for (int i = 0; i < 2; i++)
        #pragma unroll
        for (int j = 0; j < 8; j++)
            #pragma unroll
            for (int x = 0; x < 4; x++) acc[i][j][x] = 0.f;

    // ldmatrix source addresses (element offsets within a stage)
    const int aRowOff0 = (wm*32 + (lid & 15)) * PADK + (lid >> 4) * 8;
    const int aRowOff1 = aRowOff0 + 16 * PADK;
    const int bRowBase = (wn*64 + ((lid >> 4) & 1) * 8 + (lid & 7)) * PADK
                       + ((lid >> 3) & 1) * 8;

    // preload tile 0
    {
        cp16(aBase + (0*TILE_ELEMS + ldr0*PADK + ldc0)*2, Ag + (size_t)ldr0*K3 + ldc0);
        cp16(bBase + (0*TILE_ELEMS + ldr0*PADK + ldc0)*2, Wg + (size_t)ldr0*K3 + ldc0);
        cp16(aBase + (0*TILE_ELEMS + ldr1*PADK + ldc1)*2, Ag + (size_t)ldr1*K3 + ldc1);
        cp16(bBase + (0*TILE_ELEMS + ldr1*PADK + ldc1)*2, Wg + (size_t)ldr1*K3 + ldc1);
        asm volatile("cp.async.commit_group;");
    }

    for (int t = 0; t < ntiles; t++) {
        if (t + 1 < ntiles) {
            int st = (t + 1) & 1;
            const __nv_bfloat16* Agt = Ag + (size_t)(t + 1) * 32;
            const __nv_bfloat16* Wgt = Wg + (size_t)(t + 1) * 32;
            cp16(aBase + (st*TILE_ELEMS + ldr0*PADK + ldc0)*2, Agt + (size_t)ldr0*K3 + ldc0);
            cp16(bBase + (st*TILE_ELEMS + ldr0*PADK + ldc0)*2, Wgt + (size_t)ldr0*K3 + ldc0);
            cp16(aBase + (st*TILE_ELEMS + ldr1*PADK + ldc1)*2, Agt + (size_t)ldr1*K3 + ldc1);
            cp16(bBase + (st*TILE_ELEMS + ldr1*PADK + ldc1)*2, Wgt + (size_t)ldr1*K3 + ldc1);
            asm volatile("cp.async.commit_group;");
            asm volatile("cp.async.wait_group 1;");
        } else {
            asm volatile("cp.async.wait_group 0;");
        }
        __syncthreads();

        uint32_t aS = aBase + (uint32_t)(t & 1) * TILE_ELEMS * 2;
        uint32_t bS = bBase + (uint32_t)(t & 1) * TILE_ELEMS * 2;

        #pragma unroll
        for (int ks = 0; ks < 2; ks++) {
            uint32_t afr[2][4];
            ldm_x4(afr[0], aS + (uint32_t)(aRowOff0 + ks*16) * 2);
            ldm_x4(afr[1], aS + (uint32_t)(aRowOff1 + ks*16) * 2);
            uint32_t bfr[4][4];
            #pragma unroll
            for (int np = 0; np < 4; np++)
                ldm_x4(bfr[np], bS + (uint32_t)(bRowBase + np*16*PADK + ks*16) * 2);
            #pragma unroll
            for (int mt = 0; mt < 2; mt++)
                #pragma unroll
                for (int np = 0; np < 4; np++) {
                    mma16816(acc[mt][2*np],     afr[mt], &bfr[np][0]);
                    mma16816(acc[mt][2*np + 1], afr[mt], &bfr[np][2]);
                }
        }
        __syncthreads();
    }

    // Epilogue: thread holds D[r, c], D[r, c+1], D[r+8, c], D[r+8, c+1] per tile
    #pragma unroll
    for (int mt = 0; mt < 2; mt++) {
        int rbase = m0 + wm*32 + mt*16 + (lid >> 2);
        #pragma unroll
        for (int nt = 0; nt < 8; nt++) {
            int c = n0 + wn*64 + nt*8 + (lid & 3)*2;
            #pragma unroll
            for (int half = 0; half < 2; half++) {
                int n = rbase + half*8;
                float v0 = acc[mt][nt][2*half + 0];
                float v1 = acc[mt][nt][2*half + 1];
                if (MODE == 1) {
                    int b = n >> 11, m = n & 2047;
                    int which = c >> 10, rem = c & 1023;
                    int hh = rem >> 6, d0 = rem & 63;
                    float* dst = ((which == 0) ? qout : (which == 1) ? kout : vout)
                               + ((size_t)(((b << 4) + hh) * MM + m)) * DH + d0;
                    float2 o; o.x = v0 + bias[c]; o.y = v1 + bias[c + 1];
                    *(float2*)dst = o;
                } else {
                    float* cr = C + (size_t)n * Ndim + c;
                    if (MODE == 2) {
                        const float2 rv = *(const float2*)(resid + (size_t)n * Ndim + c);
                        v0 += rv.x; v1 += rv.y;
                    }
                    float2 o; o.x = v0; o.y = v1;
                    *(float2*)cr = o;
                }
            }
        }
    }
}

// ---------------- LayerNorm ---------------------------------------------------
__inline__ __device__ float warpsum(float v) {
    #pragma unroll
    for (int o = 16; o; o >>= 1) v += __shfl_xor_sync(0xffffffff, v, o);
    return v;
}

__global__ __launch_bounds__(256) void ln_kernel(
    const float* __restrict__ x, const float* __restrict__ w,
    const float* __restrict__ b, float* __restrict__ out)
{
    __shared__ float red[2][8];
    int row = blockIdx.x;
    const float4* xr = (const float4*)(x + (size_t)row * DD);
    float4 v = xr[threadIdx.x];
    float s  = v.x + v.y + v.z + v.w;
    float ss = v.x*v.x + v.y*v.y + v.z*v.z + v.w*v.w;
    s = warpsum(s); ss = warpsum(ss);
    int wid = threadIdx.x >> 5, lid = threadIdx.x & 31;
    if (lid == 0) { red[0][wid] = s; red[1][wid] = ss; }
    __syncthreads();
    if (wid == 0) {
        float a = (lid < 8) ? red[0][lid] : 0.f;
        float c = (lid < 8) ? red[1][lid] : 0.f;
        a = warpsum(a); c = warpsum(c);
        if (lid == 0) { red[0][0] = a; red[1][0] = c; }
    }
    __syncthreads();
    float mean = red[0][0] * (1.0f/DD);
    float var  = red[1][0] * (1.0f/DD) - mean*mean;
    float rstd = rsqrtf(var + 1e-5f);
    float4 wv = ((const float4*)w)[threadIdx.x];
    float4 bv = ((const float4*)b)[threadIdx.x];
    float4 o;
    o.x = (v.x - mean)*rstd*wv.x + bv.x;
    o.y = (v.y - mean)*rstd*wv.y + bv.y;
    o.z = (v.z - mean)*rstd*wv.z + bv.z;
    o.w = (v.w - mean)*rstd*wv.w + bv.w;
    ((float4*)(out + (size_t)row * DD))[threadIdx.x] = o;
}

// ---------------- RoPE --------------------------------------------------------
__global__ void rope_kernel(float* __restrict__ q, float* __restrict__ k)
{
    int gid = blockIdx.x * blockDim.x + threadIdx.x;   // over B*H*M*32
    int i = gid & 31;
    int r = gid >> 5;
    int m = r & (MM - 1);
    float invf = (float)exp2(-(double)i * (13.287712379549449 / 32.0));
    float angle = (float)m * invf;
    float sv, cv;
    sincosf(angle, &sv, &cv);
    size_t base = (size_t)r * DH + i;
    float q1 = q[base], q2 = q[base + 32];
    q[base]      = q1 * cv - q2 * sv;
    q[base + 32] = q1 * sv + q2 * cv;
    float k1 = k[base], k2 = k[base + 32];
    k[base]      = k1 * cv - k2 * sv;
    k[base + 32] = k1 * sv + k2 * cv;
}

// ---------------- Flash attention (FFMA2): 1 query/thread, 32-key tiles ------
struct alignas(16) U2 { unsigned long long a, b; };
__device__ __forceinline__ void ffma2(unsigned long long& c,
                                      unsigned long long x, unsigned long long y) {
    asm("fma.rn.f32x2 %0, %1, %2, %0;" : "+l"(c) : "l"(x), "l"(y));
}
__device__ __forceinline__ void fmul2(unsigned long long& c, unsigned long long x) {
    asm("mul.rn.f32x2 %0, %0, %1;" : "+l"(c) : "l"(x));
}
__device__ __forceinline__ unsigned long long pack2(float x, float y) {
    unsigned long long r;
    asm("mov.b64 %0, {%1,%2};" : "=l"(r) : "f"(x), "f"(y));
    return r;
}
__device__ __forceinline__ float2 unpack2(unsigned long long v) {
    float2 r;
    asm("mov.b64 {%0,%1}, %2;" : "=f"(r.x), "=f"(r.y) : "l"(v));
    return r;
}

#define TQ 128
#define TK 32
__global__ __launch_bounds__(128) void attn_kernel(
    const float* __restrict__ Q, const float* __restrict__ Kg,
    const float* __restrict__ Vg, const int* __restrict__ amask,
    float* __restrict__ out)
{
    __shared__ float Ks[TK][DH];
    __shared__ float Vs[TK][DH];
    __shared__ int   msk[TK];

    int bh = blockIdx.y;
    int b = bh >> 4;
    int h = bh & 15;
    int m = blockIdx.x * TQ + threadIdx.x;

    const float* qrow = Q + ((size_t)bh * MM + m) * DH;
    unsigned long long q2[32];
    #pragma unroll
    for (int i = 0; i < 16; i++) {
        U2 t = ((const U2*)qrow)[i];
        q2[2*i] = t.a; q2[2*i+1] = t.b;
    }

    unsigned long long o2[32];
    #pragma unroll
    for (int d = 0; d < 32; d++) o2[d] = 0ULL;
    float mx = -1e30f, l = 0.f;

    const float* Kbase = Kg + (size_t)bh * MM * DH;
    const float* Vbase = Vg + (size_t)bh * MM * DH;

    for (int kt = 0; kt < MM; kt += TK) {
        for (int t = threadIdx.x; t < TK * (DH/4); t += TQ) {
            ((float4*)&Ks[0][0])[t] = ((const float4*)(Kbase + (size_t)kt * DH))[t];
            ((float4*)&Vs[0][0])[t] = ((const float4*)(Vbase + (size_t)kt * DH))[t];
        }
        if (threadIdx.x < TK) msk[threadIdx.x] = amask[b * MM + kt + threadIdx.x];
        __syncthreads();

        float s[TK];
        float tmax = mx;
        #pragma unroll 4
        for (int j = 0; j < TK; j++) {
            unsigned long long acc = 0ULL;
            const U2* kr = (const U2*)Ks[j];
            #pragma unroll
            for (int d4 = 0; d4 < 16; d4++) {
                U2 kv = kr[d4];
                ffma2(acc, q2[2*d4],   kv.a);
                ffma2(acc, q2[2*d4+1], kv.b);
            }
            float2 pr = unpack2(acc);
            float accd = pr.x + pr.y;
            s[j] = msk[j] ? accd * 0.125f : -1e30f;
            tmax = fmaxf(tmax, s[j]);
        }
        float corr = __expf(mx - tmax);
        mx = tmax;
        float psum = 0.f;
        #pragma unroll
        for (int j = 0; j < TK; j++) { s[j] = __expf(s[j] - mx); psum += s[j]; }
        l = l * corr + psum;
        unsigned long long corr2 = pack2(corr, corr);
        #pragma unroll
        for (int d = 0; d < 32; d++) fmul2(o2[d], corr2);
        #pragma unroll 4
        for (int j = 0; j < TK; j++) {
            unsigned long long pd = pack2(s[j], s[j]);
            const U2* vr = (const U2*)Vs[j];
            #pragma unroll
            for (int d4 = 0; d4 < 16; d4++) {
                U2 vv = vr[d4];
                ffma2(o2[2*d4],   pd, vv.a);
                ffma2(o2[2*d4+1], pd, vv.b);
            }
        }
        __syncthreads();
    }

    float inv = 1.0f / l;
    unsigned long long inv2 = pack2(inv, inv);
    #pragma unroll
    for (int d = 0; d < 32; d++) fmul2(o2[d], inv2);
    float* orow = out + ((size_t)(b * MM + m)) * DD + h * DH;
    #pragma unroll
    for (int d4 = 0; d4 < 16; d4++) {
        U2 ov;
        ov.a = o2[2*d4];
        ov.b = o2[2*d4+1];
        ((U2*)orow)[d4] = ov;
    }
}

// ---------------- GeGLU -------------------------------------------------------
__global__ void geglu_kernel(const float* __restrict__ g, float* __restrict__ act)
{
    int n = blockIdx.x;
    const float* gr = g + (size_t)n * WI_N;
    float* ar = act + (size_t)n * FF;
    for (int f = threadIdx.x; f < FF; f += blockDim.x) {
        float x = gr[f];
        float gate = gr[f + FF];
        float ge = 0.5f * x * (1.0f + erff(x * 0.7071067811865476f));
        ar[f] = ge * gate;
    }
}

// ---------------- launch ------------------------------------------------------
extern "C" void kernel_launch(void* const* d_in, const int* in_sizes, int n_in,
                              void* d_out, int out_size)
{
    const float* hs     = (const float*)d_in[0];
    const int*   amask  = (const int*)  d_in[1];
    const float* ln1w   = (const float*)d_in[2];
    const float* ln1b   = (const float*)d_in[3];
    const float* wqkv_w = (const float*)d_in[4];
    const float* wqkv_b = (const float*)d_in[5];
    const float* wo_w   = (const float*)d_in[6];
    const float* ln2w   = (const float*)d_in[7];
    const float* ln2b   = (const float*)d_in[8];
    const float* wi_w   = (const float*)d_in[9];
    const float* womlp  = (const float*)d_in[10];
    float* out = (float*)d_out;

    float *xn, *q, *k, *v, *attn, *xres, *h, *gg, *act;
    __nv_bfloat16 *a3, *w3;
    cudaGetSymbolAddress((void**)&xn,   g_xn);
    cudaGetSymbolAddress((void**)&q,    g_q);
    cudaGetSymbolAddress((void**)&k,    g_k);
    cudaGetSymbolAddress((void**)&v,    g_v);
    cudaGetSymbolAddress((void**)&attn, g_attn);
    cudaGetSymbolAddress((void**)&xres, g_xres);
    cudaGetSymbolAddress((void**)&h,    g_h);
    cudaGetSymbolAddress((void**)&gg,   g_g);
    cudaGetSymbolAddress((void**)&act,  g_act);
    cudaGetSymbolAddress((void**)&a3,   g_a3);
    cudaGetSymbolAddress((void**)&w3,   g_w3);

    // 1. LN1
    ln_kernel<<<NTOK, 256>>>(hs, ln1w, ln1b, xn);

    // 2. QKV: split + tensor-core gemm (scatter to q/k/v)
    {
        int tot = NTOK * DD;
        split_kernel<0><<<(tot + 255)/256, 256>>>(xn, a3, DD, tot);
        int totw = QKV_N * DD;
        split_kernel<1><<<(totw + 255)/256, 256>>>(wqkv_w, w3, DD, totw);
        bgemm_kernel<1><<<dim3(QKV_N/128, NTOK/128), 256>>>(
            a3, w3, wqkv_b, nullptr, nullptr, q, k, v, QKV_N, 3*DD);
    }

    // 3. RoPE
    rope_kernel<<<(BB*HH*MM*32)/256, 256>>>(q, k);

    // 4. Flash attention -> attn [B,M,D]
    attn_kernel<<<dim3(MM/TQ, BB*HH), TQ>>>(q, k, v, amask, attn);

    // 5. O projection + residual -> xres
    {
        int tot = NTOK * DD;
        split_kernel<0><<<(tot + 255)/256, 256>>>(attn, a3, DD, tot);
        int totw = DD * DD;
        split_kernel<1><<<(totw + 255)/256, 256>>>(wo_w, w3, DD, totw);
        bgemm_kernel<2><<<dim3(DD/128, NTOK/128), 256>>>(
            a3, w3, nullptr, hs, xres, nullptr, nullptr, nullptr, DD, 3*DD);
    }

    // 6. LN2
    ln_kernel<<<NTOK, 256>>>(xres, ln2w, ln2b, h);

    // 7. Wi gemm -> g [NTOK, 2*FF]
    {
        int tot = NTOK * DD;
        split_kernel<0><<<(tot + 255)/256, 256>>>(h, a3, DD, tot);
        int totw = WI_N * DD;
        split_kernel<1><<<(totw + 255)/256, 256>>>(wi_w, w3, DD, totw);
        bgemm_kernel<0><<<dim3(WI_N/128, NTOK/128), 256>>>(
            a3, w3, nullptr, nullptr, gg, nullptr, nullptr, nullptr, WI_N, 3*DD);
    }

    // 8. GeGLU
    geglu_kernel<<<NTOK, 256>>>(gg, act);

    // 9. Wo_mlp gemm + residual -> out
    {
        int tot = NTOK * FF;
        split_kernel<0><<<(tot + 255)/256, 256>>>(act, a3, FF, tot);
        int totw = DD * FF;
        split_kernel<1><<<(totw + 255)/256, 256>>>(womlp, w3, FF, totw);
        bgemm_kernel<2><<<dim3(DD/128, NTOK/128), 256>>>(
            a3, w3, nullptr, xres, out, nullptr, nullptr, nullptr, DD, 3*FF);
    }
}

// round 6
// speedup vs baseline: 3.0273x; 1.8534x over previous
#include <cuda_runtime.h>
#include <cuda_bf16.h>
#include <cuda_fp16.h>
#include <math.h>
#include <stdint.h>

// Problem constants
#define BB 2
#define MM 2048
#define DD 1024
#define HH 16
#define DH 64
#define FF 2624
#define NTOK (BB*MM)           // 4096
#define QKV_N (3*DD)           // 3072
#define WI_N (2*FF)            // 5248

// ---------------- scratch (device globals; no allocation allowed) -------------
__device__ float g_xn  [NTOK*DD];
__device__ float g_q   [NTOK*DD];        // [B,H,M,DH] fp32 (pre-rope)
__device__ float g_k   [NTOK*DD];
__device__ float g_v   [NTOK*DD];
__device__ float g_attn[NTOK*DD];        // [B,M,D]
__device__ float g_xres[NTOK*DD];
__device__ float g_h   [NTOK*DD];
__device__ float g_g   [NTOK*WI_N];
__device__ float g_act [NTOK*FF];
// bf16x3 split buffers for GEMMs
__device__ __align__(128) __nv_bfloat16 g_a3[(size_t)NTOK * 3 * FF];
__device__ __align__(128) __nv_bfloat16 g_w3[(size_t)WI_N * 3 * DD];
// f16 attention operands [B,H,M,DH]
__device__ __align__(128) __half g_q2[(size_t)BB*HH*MM*DH];   // pre-scaled by 0.125*log2e
__device__ __align__(128) __half g_k2[(size_t)BB*HH*MM*DH];
__device__ __align__(128) __half g_v2[(size_t)BB*HH*MM*DH];

// ---------------- PTX helpers (base compute_80 features only) -----------------
__device__ __forceinline__ uint32_t smem_u32(const void* p) {
    uint32_t a;
    asm("{ .reg .u64 t; cvta.to.shared.u64 t, %1; cvt.u32.u64 %0, t; }"
        : "=r"(a) : "l"(p));
    return a;
}
__device__ __forceinline__ void cp16(uint32_t saddr, const void* g) {
    asm volatile("cp.async.cg.shared.global [%0], [%1], 16;" :: "r"(saddr), "l"(g));
}
__device__ __forceinline__ void ldm_x4(uint32_t* r, uint32_t addr) {
    asm volatile("ldmatrix.sync.aligned.m8n8.x4.shared.b16 {%0,%1,%2,%3}, [%4];"
        : "=r"(r[0]), "=r"(r[1]), "=r"(r[2]), "=r"(r[3]) : "r"(addr));
}
__device__ __forceinline__ void ldm_x4_t(uint32_t* r, uint32_t addr) {
    asm volatile("ldmatrix.sync.aligned.m8n8.x4.trans.shared.b16 {%0,%1,%2,%3}, [%4];"
        : "=r"(r[0]), "=r"(r[1]), "=r"(r[2]), "=r"(r[3]) : "r"(addr));
}
__device__ __forceinline__ void mma16816(float* c, const uint32_t* a, const uint32_t* b) {
    asm volatile("mma.sync.aligned.m16n8k16.row.col.f32.bf16.bf16.f32 "
        "{%0,%1,%2,%3}, {%4,%5,%6,%7}, {%8,%9}, {%0,%1,%2,%3};"
        : "+f"(c[0]), "+f"(c[1]), "+f"(c[2]), "+f"(c[3])
        : "r"(a[0]), "r"(a[1]), "r"(a[2]), "r"(a[3]), "r"(b[0]), "r"(b[1]));
}
__device__ __forceinline__ void mma16816h(float* c, const uint32_t* a, const uint32_t* b) {
    asm volatile("mma.sync.aligned.m16n8k16.row.col.f32.f16.f16.f32 "
        "{%0,%1,%2,%3}, {%4,%5,%6,%7}, {%8,%9}, {%0,%1,%2,%3};"
        : "+f"(c[0]), "+f"(c[1]), "+f"(c[2]), "+f"(c[3])
        : "r"(a[0]), "r"(a[1]), "r"(a[2]), "r"(a[3]), "r"(b[0]), "r"(b[1]));
}
__device__ __forceinline__ uint32_t cvt_h2(float hi, float lo) {
    uint32_t d;
    asm("cvt.rn.f16x2.f32 %0, %1, %2;" : "=r"(d) : "f"(hi), "f"(lo));
    return d;
}
__device__ __forceinline__ uint32_t h2exp2(uint32_t x) {
    uint32_t d;
    asm("ex2.approx.f16x2 %0, %1;" : "=r"(d) : "r"(x));
    return d;
}

// ---------------- fp32 -> bf16x3 split ----------------------------------------
template<int ISW>
__global__ void split_kernel(const float* __restrict__ X,
                             __nv_bfloat16* __restrict__ Y,
                             int K, int total)
{
    int i = blockIdx.x * 256 + threadIdx.x;
    if (i >= total) return;
    int r = i / K;
    int c = i - r * K;
    float x = X[i];
    __nv_bfloat16 hb = __float2bfloat16(x);
    float h = __bfloat162float(hb);
    __nv_bfloat16 lb = __float2bfloat16(x - h);
    size_t base = (size_t)r * (3 * K) + c;
    Y[base] = hb;
    if (ISW) { Y[base + K] = hb; Y[base + 2*K] = lb; }
    else     { Y[base + K] = lb; Y[base + 2*K] = hb; }
}

// ---------------- bf16 tensor-core GEMM (unchanged from R4) -------------------
#define PADK 40
#define TILE_ELEMS (128*PADK)

template<int MODE>
__global__ __launch_bounds__(256) void bgemm_kernel(
    const __nv_bfloat16* __restrict__ A3, const __nv_bfloat16* __restrict__ W3,
    const float* __restrict__ bias, const float* __restrict__ resid,
    float* __restrict__ C,
    float* __restrict__ qout, float* __restrict__ kout, float* __restrict__ vout,
    int Ndim, int K3)
{
    __shared__ __nv_bfloat16 Asm[2][TILE_ELEMS];
    __shared__ __nv_bfloat16 Bsm[2][TILE_ELEMS];

    const int tid = threadIdx.x;
    const int wid = tid >> 5, lid = tid & 31;
    const int wm = wid >> 1, wn = wid & 1;
    const int m0 = blockIdx.y * 128, n0 = blockIdx.x * 128;

    uint32_t aBase = smem_u32(Asm);
    uint32_t bBase = smem_u32(Bsm);

    const __nv_bfloat16* Ag = A3 + (size_t)m0 * K3;
    const __nv_bfloat16* Wg = W3 + (size_t)n0 * K3;
    const int ntiles = K3 >> 5;

    const int ldr0 = tid >> 2, ldc0 = (tid & 3) * 8;
    const int ldr1 = (tid + 256) >> 2, ldc1 = ldc0;

    float acc[2][8][4];
    #pragma unroll
    for (int i = 0; i < 2; i++)
        #pragma unroll
        for (int j = 0; j < 8; j++)
            #pragma unroll
            for (int x = 0; x < 4; x++) acc[i][j][x] = 0.f;

    const int aRowOff0 = (wm*32 + (lid & 15)) * PADK + (lid >> 4) * 8;
    const int aRowOff1 = aRowOff0 + 16 * PADK;
    const int bRowBase = (wn*64 + ((lid >> 4) & 1) * 8 + (lid & 7)) * PADK
                       + ((lid >> 3) & 1) * 8;

    {
        cp16(aBase + (0*TILE_ELEMS + ldr0*PADK + ldc0)*2, Ag + (size_t)ldr0*K3 + ldc0);
        cp16(bBase + (0*TILE_ELEMS + ldr0*PADK + ldc0)*2, Wg + (size_t)ldr0*K3 + ldc0);
        cp16(aBase + (0*TILE_ELEMS + ldr1*PADK + ldc1)*2, Ag + (size_t)ldr1*K3 + ldc1);
        cp16(bBase + (0*TILE_ELEMS + ldr1*PADK + ldc1)*2, Wg + (size_t)ldr1*K3 + ldc1);
        asm volatile("cp.async.commit_group;");
    }

    for (int t = 0; t < ntiles; t++) {
        if (t + 1 < ntiles) {
            int st = (t + 1) & 1;
            const __nv_bfloat16* Agt = Ag + (size_t)(t + 1) * 32;
            const __nv_bfloat16* Wgt = Wg + (size_t)(t + 1) * 32;
            cp16(aBase + (st*TILE_ELEMS + ldr0*PADK + ldc0)*2, Agt + (size_t)ldr0*K3 + ldc0);
            cp16(bBase + (st*TILE_ELEMS + ldr0*PADK + ldc0)*2, Wgt + (size_t)ldr0*K3 + ldc0);
            cp16(aBase + (st*TILE_ELEMS + ldr1*PADK + ldc1)*2, Agt + (size_t)ldr1*K3 + ldc1);
            cp16(bBase + (st*TILE_ELEMS + ldr1*PADK + ldc1)*2, Wgt + (size_t)ldr1*K3 + ldc1);
            asm volatile("cp.async.commit_group;");
            asm volatile("cp.async.wait_group 1;");
        } else {
            asm volatile("cp.async.wait_group 0;");
        }
        __syncthreads();

        uint32_t aS = aBase + (uint32_t)(t & 1) * TILE_ELEMS * 2;
        uint32_t bS = bBase + (uint32_t)(t & 1) * TILE_ELEMS * 2;

        #pragma unroll
        for (int ks = 0; ks < 2; ks++) {
            uint32_t afr[2][4];
            ldm_x4(afr[0], aS + (uint32_t)(aRowOff0 + ks*16) * 2);
            ldm_x4(afr[1], aS + (uint32_t)(aRowOff1 + ks*16) * 2);
            uint32_t bfr[4][4];
            #pragma unroll
            for (int np = 0; np < 4; np++)
                ldm_x4(bfr[np], bS + (uint32_t)(bRowBase + np*16*PADK + ks*16) * 2);
            #pragma unroll
            for (int mt = 0; mt < 2; mt++)
                #pragma unroll
                for (int np = 0; np < 4; np++) {
                    mma16816(acc[mt][2*np],     afr[mt], &bfr[np][0]);
                    mma16816(acc[mt][2*np + 1], afr[mt], &bfr[np][2]);
                }
        }
        __syncthreads();
    }

    #pragma unroll
    for (int mt = 0; mt < 2; mt++) {
        int rbase = m0 + wm*32 + mt*16 + (lid >> 2);
        #pragma unroll
        for (int nt = 0; nt < 8; nt++) {
            int c = n0 + wn*64 + nt*8 + (lid & 3)*2;
            #pragma unroll
            for (int half = 0; half < 2; half++) {
                int n = rbase + half*8;
                float v0 = acc[mt][nt][2*half + 0];
                float v1 = acc[mt][nt][2*half + 1];
                if (MODE == 1) {
                    int b = n >> 11, m = n & 2047;
                    int which = c >> 10, rem = c & 1023;
                    int hh = rem >> 6, d0 = rem & 63;
                    float* dst = ((which == 0) ? qout : (which == 1) ? kout : vout)
                               + ((size_t)(((b << 4) + hh) * MM + m)) * DH + d0;
                    float2 o; o.x = v0 + bias[c]; o.y = v1 + bias[c + 1];
                    *(float2*)dst = o;
                } else {
                    float* cr = C + (size_t)n * Ndim + c;
                    if (MODE == 2) {
                        const float2 rv = *(const float2*)(resid + (size_t)n * Ndim + c);
                        v0 += rv.x; v1 += rv.y;
                    }
                    float2 o; o.x = v0; o.y = v1;
                    *(float2*)cr = o;
                }
            }
        }
    }
}

// ---------------- LayerNorm ---------------------------------------------------
__inline__ __device__ float warpsum(float v) {
    #pragma unroll
    for (int o = 16; o; o >>= 1) v += __shfl_xor_sync(0xffffffff, v, o);
    return v;
}

__global__ __launch_bounds__(256) void ln_kernel(
    const float* __restrict__ x, const float* __restrict__ w,
    const float* __restrict__ b, float* __restrict__ out)
{
    __shared__ float red[2][8];
    int row = blockIdx.x;
    const float4* xr = (const float4*)(x + (size_t)row * DD);
    float4 v = xr[threadIdx.x];
    float s  = v.x + v.y + v.z + v.w;
    float ss = v.x*v.x + v.y*v.y + v.z*v.z + v.w*v.w;
    s = warpsum(s); ss = warpsum(ss);
    int wid = threadIdx.x >> 5, lid = threadIdx.x & 31;
    if (lid == 0) { red[0][wid] = s; red[1][wid] = ss; }
    __syncthreads();
    if (wid == 0) {
        float a = (lid < 8) ? red[0][lid] : 0.f;
        float c = (lid < 8) ? red[1][lid] : 0.f;
        a = warpsum(a); c = warpsum(c);
        if (lid == 0) { red[0][0] = a; red[1][0] = c; }
    }
    __syncthreads();
    float mean = red[0][0] * (1.0f/DD);
    float var  = red[1][0] * (1.0f/DD) - mean*mean;
    float rstd = rsqrtf(var + 1e-5f);
    float4 wv = ((const float4*)w)[threadIdx.x];
    float4 bv = ((const float4*)b)[threadIdx.x];
    float4 o;
    o.x = (v.x - mean)*rstd*wv.x + bv.x;
    o.y = (v.y - mean)*rstd*wv.y + bv.y;
    o.z = (v.z - mean)*rstd*wv.z + bv.z;
    o.w = (v.w - mean)*rstd*wv.w + bv.w;
    ((float4*)(out + (size_t)row * DD))[threadIdx.x] = o;
}

// ---------------- RoPE + f16 convert ------------------------------------------
// Reads fp32 q,k,v [B,H,M,DH]; writes f16 q2 (pre-scaled by 0.125*log2e), k2, v2.
#define QSCALE 0.18033688011112042f   // 0.125 * log2(e)
__global__ void rope_kernel(const float* __restrict__ q, const float* __restrict__ k,
                            const float* __restrict__ v,
                            __half* __restrict__ q2, __half* __restrict__ k2,
                            __half* __restrict__ v2)
{
    int gid = blockIdx.x * blockDim.x + threadIdx.x;   // over B*H*M*32
    int i = gid & 31;
    int r = gid >> 5;
    int m = r & (MM - 1);
    float invf = (float)exp2(-(double)i * (13.287712379549449 / 32.0));
    float angle = (float)m * invf;
    float sv, cv;
    sincosf(angle, &sv, &cv);
    size_t base = (size_t)r * DH + i;
    float q1 = q[base], qq2 = q[base + 32];
    q2[base]      = __float2half((q1 * cv - qq2 * sv) * QSCALE);
    q2[base + 32] = __float2half((q1 * sv + qq2 * cv) * QSCALE);
    float k1 = k[base], kk2 = k[base + 32];
    k2[base]      = __float2half(k1 * cv - kk2 * sv);
    k2[base + 32] = __float2half(k1 * sv + kk2 * cv);
    v2[base]      = __float2half(v[base]);
    v2[base + 32] = __float2half(v[base + 32]);
}

// ---------------- Flash attention: f16 mma.sync, exp2-domain softmax ----------
// CTA: 128 threads (4 warps), 64 queries; key tiles of 64, double-buffered.
#define ASTR 72     // smem row stride in f16 elems (64 + 8 pad)
__global__ __launch_bounds__(128) void attn_kernel(
    const __half* __restrict__ Q2, const __half* __restrict__ K2,
    const __half* __restrict__ V2, const int* __restrict__ amask,
    float* __restrict__ out)
{
    __shared__ __half Qs[64][ASTR];
    __shared__ __half Ks[2][64][ASTR];
    __shared__ __half Vs[2][64][ASTR];
    __shared__ __half2 Ms[2][32];

    const int tid = threadIdx.x, wid = tid >> 5, lid = tid & 31;
    const int bh = blockIdx.y;
    const int b = bh >> 4, h = bh & 15;
    const int q0 = blockIdx.x * 64;

    uint32_t qB = smem_u32(Qs);
    uint32_t kB = smem_u32(Ks);
    uint32_t vB = smem_u32(Vs);

    const __half* Qg = Q2 + ((size_t)bh * MM + q0) * DH;
    const __half* Kg = K2 + (size_t)bh * MM * DH;
    const __half* Vg = V2 + (size_t)bh * MM * DH;

    // preload Q + K0/V0 + mask0
    #pragma unroll
    for (int j = 0; j < 4; j++) {
        int idx = tid + j * 128;
        int row = idx >> 3, ch = (idx & 7) * 8;
        cp16(qB + (row*ASTR + ch)*2, Qg + row*DH + ch);
        cp16(kB + (row*ASTR + ch)*2, Kg + row*DH + ch);
        cp16(vB + (row*ASTR + ch)*2, Vg + row*DH + ch);
    }
    if (tid < 32) {
        int ka = amask[b*MM + 2*tid], kb2 = amask[b*MM + 2*tid + 1];
        Ms[0][tid] = __halves2half2(__int2half_rn(ka ? 1 : 0), __int2half_rn(kb2 ? 1 : 0));
    }
    asm volatile("cp.async.commit_group;");

    float o[8][4];
    #pragma unroll
    for (int f = 0; f < 8; f++)
        #pragma unroll
        for (int j = 0; j < 4; j++) o[f][j] = 0.f;
    float lr0 = 0.f, lr1 = 0.f;

    // ldmatrix address precomputes
    const uint32_t aAddrBase = qB + ((uint32_t)(wid*16 + (lid & 15)) * ASTR + (lid >> 4) * 8) * 2;
    const uint32_t bRowOff = ((uint32_t)(((lid >> 4) & 1) * 8 + (lid & 7)) * ASTR + ((lid >> 3) & 1) * 8) * 2;
    const uint32_t vRowOff = ((uint32_t)(lid & 15) * ASTR + (lid >> 4) * 8) * 2;

    for (int kt = 0; kt < 32; kt++) {
        int s = kt & 1;
        if (kt + 1 < 32) {
            int s2 = s ^ 1;
            const __half* Kn = Kg + (size_t)(kt + 1) * 64 * DH;
            const __half* Vn = Vg + (size_t)(kt + 1) * 64 * DH;
            #pragma unroll
            for (int j = 0; j < 4; j++) {
                int idx = tid + j * 128;
                int row = idx >> 3, ch = (idx & 7) * 8;
                cp16(kB + (s2*64*ASTR + row*ASTR + ch)*2, Kn + row*DH + ch);
                cp16(vB + (s2*64*ASTR + row*ASTR + ch)*2, Vn + row*DH + ch);
            }
            if (tid < 32) {
                int kbase = b*MM + (kt + 1)*64;
                int ka = amask[kbase + 2*tid], kb2 = amask[kbase + 2*tid + 1];
                Ms[s2][tid] = __halves2half2(__int2half_rn(ka ? 1 : 0), __int2half_rn(kb2 ? 1 : 0));
            }
            asm volatile("cp.async.commit_group;");
            asm volatile("cp.async.wait_group 1;");
        } else {
            asm volatile("cp.async.wait_group 0;");
        }
        __syncthreads();

        uint32_t kS = kB + (uint32_t)s * 64 * ASTR * 2;
        uint32_t vS = vB + (uint32_t)s * 64 * ASTR * 2;

        // S = (Q*C) . K^T   (log2 domain)
        float sacc[8][4];
        #pragma unroll
        for (int f = 0; f < 8; f++)
            #pragma unroll
            for (int j = 0; j < 4; j++) sacc[f][j] = 0.f;

        #pragma unroll
        for (int kk = 0; kk < 4; kk++) {
            uint32_t aq[4];
            ldm_x4(aq, aAddrBase + (uint32_t)(kk * 16) * 2);
            #pragma unroll
            for (int np = 0; np < 4; np++) {
                uint32_t bk[4];
                ldm_x4(bk, kS + (uint32_t)(np * 16) * ASTR * 2 + bRowOff + (uint32_t)(kk * 16) * 2);
                mma16816h(sacc[2*np],     aq, &bk[0]);
                mma16816h(sacc[2*np + 1], aq, &bk[2]);
            }
        }

        // softmax weights: p = 2^t * mask   (f16x2; result IS the PV A-fragment)
        uint32_t p0[8], p1[8];
        __half2 l2a = __halves2half2(__float2half(0.f), __float2half(0.f));
        __half2 l2b = l2a;
        #pragma unroll
        for (int f = 0; f < 8; f++) {
            __half2 m2 = Ms[s][4*f + (lid & 3)];
            __half2 e0 = __hmul2(*(__half2*)&(uint32_t&)*(uint32_t[]){h2exp2(cvt_h2(sacc[f][1], sacc[f][0]))}, m2);
            __half2 e1 = __hmul2(*(__half2*)&(uint32_t&)*(uint32_t[]){h2exp2(cvt_h2(sacc[f][3], sacc[f][2]))}, m2);
            p0[f] = *(uint32_t*)&e0;
            p1[f] = *(uint32_t*)&e1;
            l2a = __hadd2(l2a, e0);
            l2b = __hadd2(l2b, e1);
        }
        lr0 += __low2float(l2a) + __high2float(l2a);
        lr1 += __low2float(l2b) + __high2float(l2b);

        // O += P . V
        #pragma unroll
        for (int kk = 0; kk < 4; kk++) {
            uint32_t A[4] = { p0[2*kk], p1[2*kk], p0[2*kk + 1], p1[2*kk + 1] };
            #pragma unroll
            for (int np = 0; np < 4; np++) {
                uint32_t bv[4];
                ldm_x4_t(bv, vS + (uint32_t)(kk * 16) * ASTR * 2 + vRowOff + (uint32_t)(np * 16) * 2);
                mma16816h(o[2*np],     A, &bv[0]);
                mma16816h(o[2*np + 1], A, &bv[2]);
            }
        }
        __syncthreads();
    }

    // row-sum reduce over the quad holding each row
    lr0 += __shfl_xor_sync(0xffffffff, lr0, 1);
    lr0 += __shfl_xor_sync(0xffffffff, lr0, 2);
    lr1 += __shfl_xor_sync(0xffffffff, lr1, 1);
    lr1 += __shfl_xor_sync(0xffffffff, lr1, 2);
    float inv0 = 1.0f / lr0, inv1 = 1.0f / lr1;

    int gm0 = q0 + wid*16 + (lid >> 2);
    int gm1 = gm0 + 8;
    float* o0p = out + ((size_t)(b * MM + gm0)) * DD + h * DH;
    float* o1p = out + ((size_t)(b * MM + gm1)) * DD + h * DH;
    #pragma unroll
    for (int f = 0; f < 8; f++) {
        int c = 8*f + (lid & 3)*2;
        float2 w0; w0.x = o[f][0]*inv0; w0.y = o[f][1]*inv0;
        float2 w1; w1.x = o[f][2]*inv1; w1.y = o[f][3]*inv1;
        *(float2*)(o0p + c) = w0;
        *(float2*)(o1p + c) = w1;
    }
}

// ---------------- GeGLU -------------------------------------------------------
__global__ void geglu_kernel(const float* __restrict__ g, float* __restrict__ act)
{
    int n = blockIdx.x;
    const float* gr = g + (size_t)n * WI_N;
    float* ar = act + (size_t)n * FF;
    for (int f = threadIdx.x; f < FF; f += blockDim.x) {
        float x = gr[f];
        float gate = gr[f + FF];
        float ge = 0.5f * x * (1.0f + erff(x * 0.7071067811865476f));
        ar[f] = ge * gate;
    }
}

// ---------------- launch ------------------------------------------------------
extern "C" void kernel_launch(void* const* d_in, const int* in_sizes, int n_in,
                              void* d_out, int out_size)
{
    const float* hs     = (const float*)d_in[0];
    const int*   amask  = (const int*)  d_in[1];
    const float* ln1w   = (const float*)d_in[2];
    const float* ln1b   = (const float*)d_in[3];
    const float* wqkv_w = (const float*)d_in[4];
    const float* wqkv_b = (const float*)d_in[5];
    const float* wo_w   = (const float*)d_in[6];
    const float* ln2w   = (const float*)d_in[7];
    const float* ln2b   = (const float*)d_in[8];
    const float* wi_w   = (const float*)d_in[9];
    const float* womlp  = (const float*)d_in[10];
    float* out = (float*)d_out;

    float *xn, *q, *k, *v, *attn, *xres, *h, *gg, *act;
    __nv_bfloat16 *a3, *w3;
    __half *q2, *k2, *v2;
    cudaGetSymbolAddress((void**)&xn,   g_xn);
    cudaGetSymbolAddress((void**)&q,    g_q);
    cudaGetSymbolAddress((void**)&k,    g_k);
    cudaGetSymbolAddress((void**)&v,    g_v);
    cudaGetSymbolAddress((void**)&attn, g_attn);
    cudaGetSymbolAddress((void**)&xres, g_xres);
    cudaGetSymbolAddress((void**)&h,    g_h);
    cudaGetSymbolAddress((void**)&gg,   g_g);
    cudaGetSymbolAddress((void**)&act,  g_act);
    cudaGetSymbolAddress((void**)&a3,   g_a3);
    cudaGetSymbolAddress((void**)&w3,   g_w3);
    cudaGetSymbolAddress((void**)&q2,   g_q2);
    cudaGetSymbolAddress((void**)&k2,   g_k2);
    cudaGetSymbolAddress((void**)&v2,   g_v2);

    // 1. LN1
    ln_kernel<<<NTOK, 256>>>(hs, ln1w, ln1b, xn);

    // 2. QKV: split + tensor-core gemm (scatter to q/k/v fp32)
    {
        int tot = NTOK * DD;
        split_kernel<0><<<(tot + 255)/256, 256>>>(xn, a3, DD, tot);
        int totw = QKV_N * DD;
        split_kernel<1><<<(totw + 255)/256, 256>>>(wqkv_w, w3, DD, totw);
        bgemm_kernel<1><<<dim3(QKV_N/128, NTOK/128), 256>>>(
            a3, w3, wqkv_b, nullptr, nullptr, q, k, v, QKV_N, 3*DD);
    }

    // 3. RoPE + f16 conversion (q pre-scaled to log2 score domain)
    rope_kernel<<<(BB*HH*MM*32)/256, 256>>>(q, k, v, q2, k2, v2);

    // 4. Flash attention (f16 tensor cores) -> attn [B,M,D] fp32
    attn_kernel<<<dim3(MM/64, BB*HH), 128>>>(q2, k2, v2, amask, attn);

    // 5. O projection + residual -> xres
    {
        int tot = NTOK * DD;
        split_kernel<0><<<(tot + 255)/256, 256>>>(attn, a3, DD, tot);
        int totw = DD * DD;
        split_kernel<1><<<(totw + 255)/256, 256>>>(wo_w, w3, DD, totw);
        bgemm_kernel<2><<<dim3(DD/128, NTOK/128), 256>>>(
            a3, w3, nullptr, hs, xres, nullptr, nullptr, nullptr, DD, 3*DD);
    }

    // 6. LN2
    ln_kernel<<<NTOK, 256>>>(xres, ln2w, ln2b, h);

    // 7. Wi gemm -> g [NTOK, 2*FF]
    {
        int tot = NTOK * DD;
        split_kernel<0><<<(tot + 255)/256, 256>>>(h, a3, DD, tot);
        int totw = WI_N * DD;
        split_kernel<1><<<(totw + 255)/256, 256>>>(wi_w, w3, DD, totw);
        bgemm_kernel<0><<<dim3(WI_N/128, NTOK/128), 256>>>(
            a3, w3, nullptr, nullptr, gg, nullptr, nullptr, nullptr, WI_N, 3*DD);
    }

    // 8. GeGLU
    geglu_kernel<<<NTOK, 256>>>(gg, act);

    // 9. Wo_mlp gemm + residual -> out
    {
        int tot = NTOK * FF;
        split_kernel<0><<<(tot + 255)/256, 256>>>(act, a3, FF, tot);
        int totw = DD * FF;
        split_kernel<1><<<(totw + 255)/256, 256>>>(womlp, w3, FF, totw);
        bgemm_kernel<2><<<dim3(DD/128, NTOK/128), 256>>>(
            a3, w3, nullptr, xres, out, nullptr, nullptr, nullptr, DD, 3*FF);
    }
}

// round 7
// speedup vs baseline: 3.3014x; 1.0905x over previous
#include <cuda_runtime.h>
#include <cuda_bf16.h>
#include <cuda_fp16.h>
#include <math.h>
#include <stdint.h>

// Problem constants
#define BB 2
#define MM 2048
#define DD 1024
#define HH 16
#define DH 64
#define FF 2624
#define NTOK (BB*MM)           // 4096
#define QKV_N (3*DD)           // 3072
#define WI_N (2*FF)            // 5248

// ---------------- scratch (device globals; no allocation allowed) -------------
__device__ float g_q   [NTOK*DD];        // [B,H,M,DH] fp32 (pre-rope)
__device__ float g_k   [NTOK*DD];
__device__ float g_v   [NTOK*DD];
__device__ float g_xres[NTOK*DD];
__device__ float g_g   [NTOK*WI_N];
// bf16x3 split buffers
__device__ __align__(128) __nv_bfloat16 g_a3[(size_t)NTOK * 3 * FF];
__device__ __align__(128) __nv_bfloat16 g_w3[(size_t)WI_N * 3 * DD];
// f16 attention operands [B,H,M,DH]
__device__ __align__(128) __half g_q2[(size_t)BB*HH*MM*DH];
__device__ __align__(128) __half g_k2[(size_t)BB*HH*MM*DH];
__device__ __align__(128) __half g_v2[(size_t)BB*HH*MM*DH];

// ---------------- PTX helpers (base compute_80 features only) -----------------
__device__ __forceinline__ uint32_t smem_u32(const void* p) {
    uint32_t a;
    asm("{ .reg .u64 t; cvta.to.shared.u64 t, %1; cvt.u32.u64 %0, t; }"
        : "=r"(a) : "l"(p));
    return a;
}
__device__ __forceinline__ void cp16(uint32_t saddr, const void* g) {
    asm volatile("cp.async.cg.shared.global [%0], [%1], 16;" :: "r"(saddr), "l"(g));
}
__device__ __forceinline__ void ldm_x4(uint32_t* r, uint32_t addr) {
    asm volatile("ldmatrix.sync.aligned.m8n8.x4.shared.b16 {%0,%1,%2,%3}, [%4];"
        : "=r"(r[0]), "=r"(r[1]), "=r"(r[2]), "=r"(r[3]) : "r"(addr));
}
__device__ __forceinline__ void ldm_x4_t(uint32_t* r, uint32_t addr) {
    asm volatile("ldmatrix.sync.aligned.m8n8.x4.trans.shared.b16 {%0,%1,%2,%3}, [%4];"
        : "=r"(r[0]), "=r"(r[1]), "=r"(r[2]), "=r"(r[3]) : "r"(addr));
}
__device__ __forceinline__ void mma16816(float* c, const uint32_t* a, const uint32_t* b) {
    asm volatile("mma.sync.aligned.m16n8k16.row.col.f32.bf16.bf16.f32 "
        "{%0,%1,%2,%3}, {%4,%5,%6,%7}, {%8,%9}, {%0,%1,%2,%3};"
        : "+f"(c[0]), "+f"(c[1]), "+f"(c[2]), "+f"(c[3])
        : "r"(a[0]), "r"(a[1]), "r"(a[2]), "r"(a[3]), "r"(b[0]), "r"(b[1]));
}
__device__ __forceinline__ void mma16816h(float* c, const uint32_t* a, const uint32_t* b) {
    asm volatile("mma.sync.aligned.m16n8k16.row.col.f32.f16.f16.f32 "
        "{%0,%1,%2,%3}, {%4,%5,%6,%7}, {%8,%9}, {%0,%1,%2,%3};"
        : "+f"(c[0]), "+f"(c[1]), "+f"(c[2]), "+f"(c[3])
        : "r"(a[0]), "r"(a[1]), "r"(a[2]), "r"(a[3]), "r"(b[0]), "r"(b[1]));
}
__device__ __forceinline__ uint32_t cvt_h2(float hi, float lo) {
    uint32_t d;
    asm("cvt.rn.f16x2.f32 %0, %1, %2;" : "=r"(d) : "f"(hi), "f"(lo));
    return d;
}
__device__ __forceinline__ uint32_t h2exp2(uint32_t x) {
    uint32_t d;
    asm("ex2.approx.f16x2 %0, %1;" : "=r"(d) : "r"(x));
    return d;
}
// bf16x3 element write: activation layout [hi | lo | hi], row stride 3K
__device__ __forceinline__ void write_a3_pair(__nv_bfloat16* rowp, int c, int K,
                                              float x, float y) {
    __nv_bfloat162 hi; hi.x = __float2bfloat16(x); hi.y = __float2bfloat16(y);
    __nv_bfloat162 lo;
    lo.x = __float2bfloat16(x - __bfloat162float(hi.x));
    lo.y = __float2bfloat16(y - __bfloat162float(hi.y));
    *(__nv_bfloat162*)(rowp + c)         = hi;
    *(__nv_bfloat162*)(rowp + c + K)     = lo;
    *(__nv_bfloat162*)(rowp + c + 2*K)   = hi;
}

// ---------------- fp32 -> bf16x3 split (weights only now) ---------------------
__global__ void splitw_kernel(const float* __restrict__ X,
                              __nv_bfloat16* __restrict__ Y,
                              int K, int total)
{
    int i = blockIdx.x * 256 + threadIdx.x;
    if (i >= total) return;
    int r = i / K;
    int c = i - r * K;
    float x = X[i];
    __nv_bfloat16 hb = __float2bfloat16(x);
    float h = __bfloat162float(hb);
    __nv_bfloat16 lb = __float2bfloat16(x - h);
    size_t base = (size_t)r * (3 * K) + c;
    Y[base] = hb;
    Y[base + K] = hb;
    Y[base + 2*K] = lb;
}

// ---------------- bf16 tensor-core GEMM, 4-stage cp.async pipeline ------------
// 128x128 CTA tile, 8 warps (4m x 2n), warp tile 32x64, K-tile 32.
// MODE 0: C = acc; MODE 1: QKV scatter + bias; MODE 2: C = acc + resid
#define PADK 40
#define STAGES 4
#define AB_BYTES (128*PADK*2)               // 10240 per operand per stage
#define STAGE_BYTES (2*AB_BYTES)            // 20480
#define BG_SMEM (STAGES*STAGE_BYTES)        // 81920

template<int MODE>
__global__ __launch_bounds__(256) void bgemm_kernel(
    const __nv_bfloat16* __restrict__ A3, const __nv_bfloat16* __restrict__ W3,
    const float* __restrict__ bias, const float* __restrict__ resid,
    float* __restrict__ C,
    float* __restrict__ qout, float* __restrict__ kout, float* __restrict__ vout,
    int Ndim, int K3)
{
    extern __shared__ char dynsmem[];
    const uint32_t base = smem_u32(dynsmem);

    const int tid = threadIdx.x;
    const int wid = tid >> 5, lid = tid & 31;
    const int wm = wid >> 1, wn = wid & 1;
    const int m0 = blockIdx.y * 128, n0 = blockIdx.x * 128;

    const __nv_bfloat16* Ag = A3 + (size_t)m0 * K3;
    const __nv_bfloat16* Wg = W3 + (size_t)n0 * K3;
    const int ntiles = K3 >> 5;

    const int ldr0 = tid >> 2, ldc0 = (tid & 3) * 8;
    const int ldr1 = (tid + 256) >> 2;
    const uint32_t so0 = (uint32_t)(ldr0*PADK + ldc0) * 2;
    const uint32_t so1 = (uint32_t)(ldr1*PADK + ldc0) * 2;

    float acc[2][8][4];
    #pragma unroll
    for (int i = 0; i < 2; i++)
        #pragma unroll
        for (int j = 0; j < 8; j++)
            #pragma unroll
            for (int x = 0; x < 4; x++) acc[i][j][x] = 0.f;

    const int aRowOff0 = (wm*32 + (lid & 15)) * PADK + (lid >> 4) * 8;
    const int aRowOff1 = aRowOff0 + 16 * PADK;
    const int bRowBase = (wn*64 + ((lid >> 4) & 1) * 8 + (lid & 7)) * PADK
                       + ((lid >> 3) & 1) * 8;

    // prologue: stages 0..2
    #pragma unroll
    for (int t = 0; t < STAGES - 1; t++) {
        uint32_t sb = base + (uint32_t)t * STAGE_BYTES;
        const __nv_bfloat16* Agt = Ag + (size_t)t * 32;
        const __nv_bfloat16* Wgt = Wg + (size_t)t * 32;
        cp16(sb + so0,            Agt + (size_t)ldr0*K3 + ldc0);
        cp16(sb + AB_BYTES + so0, Wgt + (size_t)ldr0*K3 + ldc0);
        cp16(sb + so1,            Agt + (size_t)ldr1*K3 + ldc0);
        cp16(sb + AB_BYTES + so1, Wgt + (size_t)ldr1*K3 + ldc0);
        asm volatile("cp.async.commit_group;");
    }

    for (int t = 0; t < ntiles; t++) {
        asm volatile("cp.async.wait_group %0;" :: "n"(STAGES - 2));
        __syncthreads();

        if (t + STAGES - 1 < ntiles) {
            int tp = t + STAGES - 1;
            uint32_t sb = base + (uint32_t)(tp & (STAGES-1)) * STAGE_BYTES;
            const __nv_bfloat16* Agt = Ag + (size_t)tp * 32;
            const __nv_bfloat16* Wgt = Wg + (size_t)tp * 32;
            cp16(sb + so0,            Agt + (size_t)ldr0*K3 + ldc0);
            cp16(sb + AB_BYTES + so0, Wgt + (size_t)ldr0*K3 + ldc0);
            cp16(sb + so1,            Agt + (size_t)ldr1*K3 + ldc0);
            cp16(sb + AB_BYTES + so1, Wgt + (size_t)ldr1*K3 + ldc0);
        }
        asm volatile("cp.async.commit_group;");

        uint32_t aS = base + (uint32_t)(t & (STAGES-1)) * STAGE_BYTES;
        uint32_t bS = aS + AB_BYTES;

        #pragma unroll
        for (int ks = 0; ks < 2; ks++) {
            uint32_t afr[2][4];
            ldm_x4(afr[0], aS + (uint32_t)(aRowOff0 + ks*16) * 2);
            ldm_x4(afr[1], aS + (uint32_t)(aRowOff1 + ks*16) * 2);
            uint32_t bfr[4][4];
            #pragma unroll
            for (int np = 0; np < 4; np++)
                ldm_x4(bfr[np], bS + (uint32_t)(bRowBase + np*16*PADK + ks*16) * 2);
            #pragma unroll
            for (int mt = 0; mt < 2; mt++)
                #pragma unroll
                for (int np = 0; np < 4; np++) {
                    mma16816(acc[mt][2*np],     afr[mt], &bfr[np][0]);
                    mma16816(acc[mt][2*np + 1], afr[mt], &bfr[np][2]);
                }
        }
    }

    #pragma unroll
    for (int mt = 0; mt < 2; mt++) {
        int rbase = m0 + wm*32 + mt*16 + (lid >> 2);
        #pragma unroll
        for (int nt = 0; nt < 8; nt++) {
            int c = n0 + wn*64 + nt*8 + (lid & 3)*2;
            #pragma unroll
            for (int half = 0; half < 2; half++) {
                int n = rbase + half*8;
                float v0 = acc[mt][nt][2*half + 0];
                float v1 = acc[mt][nt][2*half + 1];
                if (MODE == 1) {
                    int b = n >> 11, m = n & 2047;
                    int which = c >> 10, rem = c & 1023;
                    int hh = rem >> 6, d0 = rem & 63;
                    float* dst = ((which == 0) ? qout : (which == 1) ? kout : vout)
                               + ((size_t)(((b << 4) + hh) * MM + m)) * DH + d0;
                    float2 o; o.x = v0 + bias[c]; o.y = v1 + bias[c + 1];
                    *(float2*)dst = o;
                } else {
                    float* cr = C + (size_t)n * Ndim + c;
                    if (MODE == 2) {
                        const float2 rv = *(const float2*)(resid + (size_t)n * Ndim + c);
                        v0 += rv.x; v1 += rv.y;
                    }
                    float2 o; o.x = v0; o.y = v1;
                    *(float2*)cr = o;
                }
            }
        }
    }
}

// ---------------- LayerNorm -> bf16x3 directly --------------------------------
__inline__ __device__ float warpsum(float v) {
    #pragma unroll
    for (int o = 16; o; o >>= 1) v += __shfl_xor_sync(0xffffffff, v, o);
    return v;
}

__global__ __launch_bounds__(256) void ln_kernel(
    const float* __restrict__ x, const float* __restrict__ w,
    const float* __restrict__ b, __nv_bfloat16* __restrict__ a3)
{
    __shared__ float red[2][8];
    int row = blockIdx.x;
    const float4* xr = (const float4*)(x + (size_t)row * DD);
    float4 v = xr[threadIdx.x];
    float s  = v.x + v.y + v.z + v.w;
    float ss = v.x*v.x + v.y*v.y + v.z*v.z + v.w*v.w;
    s = warpsum(s); ss = warpsum(ss);
    int wid = threadIdx.x >> 5, lid = threadIdx.x & 31;
    if (lid == 0) { red[0][wid] = s; red[1][wid] = ss; }
    __syncthreads();
    if (wid == 0) {
        float a = (lid < 8) ? red[0][lid] : 0.f;
        float c = (lid < 8) ? red[1][lid] : 0.f;
        a = warpsum(a); c = warpsum(c);
        if (lid == 0) { red[0][0] = a; red[1][0] = c; }
    }
    __syncthreads();
    float mean = red[0][0] * (1.0f/DD);
    float var  = red[1][0] * (1.0f/DD) - mean*mean;
    float rstd = rsqrtf(var + 1e-5f);
    float4 wv = ((const float4*)w)[threadIdx.x];
    float4 bv = ((const float4*)b)[threadIdx.x];
    float o0 = (v.x - mean)*rstd*wv.x + bv.x;
    float o1 = (v.y - mean)*rstd*wv.y + bv.y;
    float o2 = (v.z - mean)*rstd*wv.z + bv.z;
    float o3 = (v.w - mean)*rstd*wv.w + bv.w;
    __nv_bfloat16* rowp = a3 + (size_t)row * (3*DD);
    int c = threadIdx.x * 4;
    write_a3_pair(rowp, c,     DD, o0, o1);
    write_a3_pair(rowp, c + 2, DD, o2, o3);
}

// ---------------- RoPE + f16 convert ------------------------------------------
#define QSCALE 0.18033688011112042f   // 0.125 * log2(e)
__global__ void rope_kernel(const float* __restrict__ q, const float* __restrict__ k,
                            const float* __restrict__ v,
                            __half* __restrict__ q2, __half* __restrict__ k2,
                            __half* __restrict__ v2)
{
    int gid = blockIdx.x * blockDim.x + threadIdx.x;   // over B*H*M*32
    int i = gid & 31;
    int r = gid >> 5;
    int m = r & (MM - 1);
    float invf = (float)exp2(-(double)i * (13.287712379549449 / 32.0));
    float angle = (float)m * invf;
    float sv, cv;
    sincosf(angle, &sv, &cv);
    size_t base = (size_t)r * DH + i;
    float q1 = q[base], qq2 = q[base + 32];
    q2[base]      = __float2half((q1 * cv - qq2 * sv) * QSCALE);
    q2[base + 32] = __float2half((q1 * sv + qq2 * cv) * QSCALE);
    float k1 = k[base], kk2 = k[base + 32];
    k2[base]      = __float2half(k1 * cv - kk2 * sv);
    k2[base + 32] = __float2half(k1 * sv + kk2 * cv);
    v2[base]      = __float2half(v[base]);
    v2[base + 32] = __float2half(v[base + 32]);
}

// ---------------- Flash attention: f16 mma.sync, epilogue -> bf16x3 -----------
#define ASTR 72
__global__ __launch_bounds__(128) void attn_kernel(
    const __half* __restrict__ Q2, const __half* __restrict__ K2,
    const __half* __restrict__ V2, const int* __restrict__ amask,
    __nv_bfloat16* __restrict__ a3)
{
    __shared__ __half Qs[64][ASTR];
    __shared__ __half Ks[2][64][ASTR];
    __shared__ __half Vs[2][64][ASTR];
    __shared__ __half2 Ms[2][32];

    const int tid = threadIdx.x, wid = tid >> 5, lid = tid & 31;
    const int bh = blockIdx.y;
    const int b = bh >> 4, h = bh & 15;
    const int q0 = blockIdx.x * 64;

    uint32_t qB = smem_u32(Qs);
    uint32_t kB = smem_u32(Ks);
    uint32_t vB = smem_u32(Vs);

    const __half* Qg = Q2 + ((size_t)bh * MM + q0) * DH;
    const __half* Kg = K2 + (size_t)bh * MM * DH;
    const __half* Vg = V2 + (size_t)bh * MM * DH;

    #pragma unroll
    for (int j = 0; j < 4; j++) {
        int idx = tid + j * 128;
        int row = idx >> 3, ch = (idx & 7) * 8;
        cp16(qB + (row*ASTR + ch)*2, Qg + row*DH + ch);
        cp16(kB + (row*ASTR + ch)*2, Kg + row*DH + ch);
        cp16(vB + (row*ASTR + ch)*2, Vg + row*DH + ch);
    }
    if (tid < 32) {
        int ka = amask[b*MM + 2*tid], kb2 = amask[b*MM + 2*tid + 1];
        Ms[0][tid] = __halves2half2(__int2half_rn(ka ? 1 : 0), __int2half_rn(kb2 ? 1 : 0));
    }
    asm volatile("cp.async.commit_group;");

    float o[8][4];
    #pragma unroll
    for (int f = 0; f < 8; f++)
        #pragma unroll
        for (int j = 0; j < 4; j++) o[f][j] = 0.f;
    float lr0 = 0.f, lr1 = 0.f;

    const uint32_t aAddrBase = qB + ((uint32_t)(wid*16 + (lid & 15)) * ASTR + (lid >> 4) * 8) * 2;
    const uint32_t bRowOff = ((uint32_t)(((lid >> 4) & 1) * 8 + (lid & 7)) * ASTR + ((lid >> 3) & 1) * 8) * 2;
    const uint32_t vRowOff = ((uint32_t)(lid & 15) * ASTR + (lid >> 4) * 8) * 2;

    for (int kt = 0; kt < 32; kt++) {
        int s = kt & 1;
        if (kt + 1 < 32) {
            int s2 = s ^ 1;
            const __half* Kn = Kg + (size_t)(kt + 1) * 64 * DH;
            const __half* Vn = Vg + (size_t)(kt + 1) * 64 * DH;
            #pragma unroll
            for (int j = 0; j < 4; j++) {
                int idx = tid + j * 128;
                int row = idx >> 3, ch = (idx & 7) * 8;
                cp16(kB + (s2*64*ASTR + row*ASTR + ch)*2, Kn + row*DH + ch);
                cp16(vB + (s2*64*ASTR + row*ASTR + ch)*2, Vn + row*DH + ch);
            }
            if (tid < 32) {
                int kbase = b*MM + (kt + 1)*64;
                int ka = amask[kbase + 2*tid], kb2 = amask[kbase + 2*tid + 1];
                Ms[s2][tid] = __halves2half2(__int2half_rn(ka ? 1 : 0), __int2half_rn(kb2 ? 1 : 0));
            }
            asm volatile("cp.async.commit_group;");
            asm volatile("cp.async.wait_group 1;");
        } else {
            asm volatile("cp.async.wait_group 0;");
        }
        __syncthreads();

        uint32_t kS = kB + (uint32_t)s * 64 * ASTR * 2;
        uint32_t vS = vB + (uint32_t)s * 64 * ASTR * 2;

        float sacc[8][4];
        #pragma unroll
        for (int f = 0; f < 8; f++)
            #pragma unroll
            for (int j = 0; j < 4; j++) sacc[f][j] = 0.f;

        #pragma unroll
        for (int kk = 0; kk < 4; kk++) {
            uint32_t aq[4];
            ldm_x4(aq, aAddrBase + (uint32_t)(kk * 16) * 2);
            #pragma unroll
            for (int np = 0; np < 4; np++) {
                uint32_t bk[4];
                ldm_x4(bk, kS + (uint32_t)(np * 16) * ASTR * 2 + bRowOff + (uint32_t)(kk * 16) * 2);
                mma16816h(sacc[2*np],     aq, &bk[0]);
                mma16816h(sacc[2*np + 1], aq, &bk[2]);
            }
        }

        uint32_t p0[8], p1[8];
        __half2 l2a = __halves2half2(__float2half(0.f), __float2half(0.f));
        __half2 l2b = l2a;
        #pragma unroll
        for (int f = 0; f < 8; f++) {
            __half2 m2 = Ms[s][4*f + (lid & 3)];
            uint32_t e0u = h2exp2(cvt_h2(sacc[f][1], sacc[f][0]));
            uint32_t e1u = h2exp2(cvt_h2(sacc[f][3], sacc[f][2]));
            __half2 e0 = __hmul2(*reinterpret_cast<__half2*>(&e0u), m2);
            __half2 e1 = __hmul2(*reinterpret_cast<__half2*>(&e1u), m2);
            p0[f] = *(uint32_t*)&e0;
            p1[f] = *(uint32_t*)&e1;
            l2a = __hadd2(l2a, e0);
            l2b = __hadd2(l2b, e1);
        }
        lr0 += __low2float(l2a) + __high2float(l2a);
        lr1 += __low2float(l2b) + __high2float(l2b);

        #pragma unroll
        for (int kk = 0; kk < 4; kk++) {
            uint32_t A[4] = { p0[2*kk], p1[2*kk], p0[2*kk + 1], p1[2*kk + 1] };
            #pragma unroll
            for (int np = 0; np < 4; np++) {
                uint32_t bv[4];
                ldm_x4_t(bv, vS + (uint32_t)(kk * 16) * ASTR * 2 + vRowOff + (uint32_t)(np * 16) * 2);
                mma16816h(o[2*np],     A, &bv[0]);
                mma16816h(o[2*np + 1], A, &bv[2]);
            }
        }
        __syncthreads();
    }

    lr0 += __shfl_xor_sync(0xffffffff, lr0, 1);
    lr0 += __shfl_xor_sync(0xffffffff, lr0, 2);
    lr1 += __shfl_xor_sync(0xffffffff, lr1, 1);
    lr1 += __shfl_xor_sync(0xffffffff, lr1, 2);
    float inv0 = 1.0f / lr0, inv1 = 1.0f / lr1;

    int gm0 = q0 + wid*16 + (lid >> 2);
    int gm1 = gm0 + 8;
    __nv_bfloat16* r0p = a3 + (size_t)(b * MM + gm0) * (3*DD) + h * DH;
    __nv_bfloat16* r1p = a3 + (size_t)(b * MM + gm1) * (3*DD) + h * DH;
    #pragma unroll
    for (int f = 0; f < 8; f++) {
        int c = 8*f + (lid & 3)*2;
        write_a3_pair(r0p, c, DD, o[f][0]*inv0, o[f][1]*inv0);
        write_a3_pair(r1p, c, DD, o[f][2]*inv1, o[f][3]*inv1);
    }
}

// ---------------- GeGLU -> bf16x3 directly ------------------------------------
__global__ void geglu_kernel(const float* __restrict__ g, __nv_bfloat16* __restrict__ a3)
{
    int n = blockIdx.x;
    const float* gr = g + (size_t)n * WI_N;
    __nv_bfloat16* rowp = a3 + (size_t)n * (3*FF);
    for (int f = threadIdx.x * 2; f < FF; f += blockDim.x * 2) {
        float2 x2 = *(const float2*)(gr + f);
        float2 gt = *(const float2*)(gr + f + FF);
        float v0 = 0.5f * x2.x * (1.0f + erff(x2.x * 0.7071067811865476f)) * gt.x;
        float v1 = 0.5f * x2.y * (1.0f + erff(x2.y * 0.7071067811865476f)) * gt.y;
        write_a3_pair(rowp, f, FF, v0, v1);
    }
}

// ---------------- launch ------------------------------------------------------
extern "C" void kernel_launch(void* const* d_in, const int* in_sizes, int n_in,
                              void* d_out, int out_size)
{
    const float* hs     = (const float*)d_in[0];
    const int*   amask  = (const int*)  d_in[1];
    const float* ln1w   = (const float*)d_in[2];
    const float* ln1b   = (const float*)d_in[3];
    const float* wqkv_w = (const float*)d_in[4];
    const float* wqkv_b = (const float*)d_in[5];
    const float* wo_w   = (const float*)d_in[6];
    const float* ln2w   = (const float*)d_in[7];
    const float* ln2b   = (const float*)d_in[8];
    const float* wi_w   = (const float*)d_in[9];
    const float* womlp  = (const float*)d_in[10];
    float* out = (float*)d_out;

    float *q, *k, *v, *xres, *gg;
    __nv_bfloat16 *a3, *w3;
    __half *q2, *k2, *v2;
    cudaGetSymbolAddress((void**)&q,    g_q);
    cudaGetSymbolAddress((void**)&k,    g_k);
    cudaGetSymbolAddress((void**)&v,    g_v);
    cudaGetSymbolAddress((void**)&xres, g_xres);
    cudaGetSymbolAddress((void**)&gg,   g_g);
    cudaGetSymbolAddress((void**)&a3,   g_a3);
    cudaGetSymbolAddress((void**)&w3,   g_w3);
    cudaGetSymbolAddress((void**)&q2,   g_q2);
    cudaGetSymbolAddress((void**)&k2,   g_k2);
    cudaGetSymbolAddress((void**)&v2,   g_v2);

    cudaFuncSetAttribute(bgemm_kernel<0>, cudaFuncAttributeMaxDynamicSharedMemorySize, BG_SMEM);
    cudaFuncSetAttribute(bgemm_kernel<1>, cudaFuncAttributeMaxDynamicSharedMemorySize, BG_SMEM);
    cudaFuncSetAttribute(bgemm_kernel<2>, cudaFuncAttributeMaxDynamicSharedMemorySize, BG_SMEM);

    // 1. LN1 -> a3 (bf16x3)
    ln_kernel<<<NTOK, 256>>>(hs, ln1w, ln1b, a3);

    // 2. QKV gemm -> q/k/v fp32
    {
        int totw = QKV_N * DD;
        splitw_kernel<<<(totw + 255)/256, 256>>>(wqkv_w, w3, DD, totw);
        bgemm_kernel<1><<<dim3(QKV_N/128, NTOK/128), 256, BG_SMEM>>>(
            a3, w3, wqkv_b, nullptr, nullptr, q, k, v, QKV_N, 3*DD);
    }

    // 3. RoPE + f16 conversion
    rope_kernel<<<(BB*HH*MM*32)/256, 256>>>(q, k, v, q2, k2, v2);

    // 4. Flash attention -> a3 (bf16x3 of attention output)
    attn_kernel<<<dim3(MM/64, BB*HH), 128>>>(q2, k2, v2, amask, a3);

    // 5. O projection + residual -> xres
    {
        int totw = DD * DD;
        splitw_kernel<<<(totw + 255)/256, 256>>>(wo_w, w3, DD, totw);
        bgemm_kernel<2><<<dim3(DD/128, NTOK/128), 256, BG_SMEM>>>(
            a3, w3, nullptr, hs, xres, nullptr, nullptr, nullptr, DD, 3*DD);
    }

    // 6. LN2 -> a3
    ln_kernel<<<NTOK, 256>>>(xres, ln2w, ln2b, a3);

    // 7. Wi gemm -> gg fp32
    {
        int totw = WI_N * DD;
        splitw_kernel<<<(totw + 255)/256, 256>>>(wi_w, w3, DD, totw);
        bgemm_kernel<0><<<dim3(WI_N/128, NTOK/128), 256, BG_SMEM>>>(
            a3, w3, nullptr, nullptr, gg, nullptr, nullptr, nullptr, WI_N, 3*DD);
    }

    // 8. GeGLU -> a3 (K=FF layout)
    geglu_kernel<<<NTOK, 256>>>(gg, a3);

    // 9. Wo_mlp gemm + residual -> out
    {
        int totw = DD * FF;
        splitw_kernel<<<(totw + 255)/256, 256>>>(womlp, w3, FF, totw);
        bgemm_kernel<2><<<dim3(DD/128, NTOK/128), 256, BG_SMEM>>>(
            a3, w3, nullptr, xres, out, nullptr, nullptr, nullptr, DD, 3*FF);
    }
}